// round 13
// baseline (speedup 1.0000x reference)
#include <cuda_runtime.h>
#include <cuda_bf16.h>
#include <cstdint>
#include <math.h>

// Problem: B=4, H=16, T=1024, D=64, E=1024, M=B*T=4096, BH=64
// GEMMs are TN (C[m,n] = sum_k A[m,k]*B[n,k]) on bf16x2 split planes.

// ---------------------------------------------------------------------------
// Device-global scratch
// ---------------------------------------------------------------------------
__device__ __nv_bfloat16 g_xs0[4194304], g_xs1[4194304];   // x split   [4096][1024]
__device__ __nv_bfloat16 g_wb0[3145728], g_wb1[3145728];   // Wq|Wk|Wv  [3072][1024]
__device__ __nv_bfloat16 g_wo0[1048576], g_wo1[1048576];   // Wo        [1024][1024]
__device__ __nv_bfloat16 g_q0[4194304],  g_q1[4194304];    // q (scaled 0.125*log2e) [bh][t][d]
__device__ __nv_bfloat16 g_k0[4194304],  g_k1[4194304];    // k  [bh][s][d]
__device__ __nv_bfloat16 g_vt0[4194304], g_vt1[4194304];   // vT [bh][d][s]
__device__ __nv_bfloat16 g_c0[4194304],  g_c1[4194304];    // ctx planes [m][e]

// ---------------------------------------------------------------------------
// PTX helpers
// ---------------------------------------------------------------------------
__device__ __forceinline__ uint32_t smem_u32(const void* p) {
    uint32_t a;
    asm("{ .reg .u64 t; cvta.to.shared.u64 t, %1; cvt.u32.u64 %0, t; }" : "=r"(a) : "l"(p));
    return a;
}

__device__ __forceinline__ void ldsm4(uint32_t r[4], uint32_t addr) {
    asm volatile("ldmatrix.sync.aligned.m8n8.x4.shared.b16 {%0,%1,%2,%3}, [%4];"
        : "=r"(r[0]), "=r"(r[1]), "=r"(r[2]), "=r"(r[3]) : "r"(addr));
}

__device__ __forceinline__ void mma_bf16(float* c, const uint32_t* a, const uint32_t* b) {
    asm volatile(
        "mma.sync.aligned.m16n8k16.row.col.f32.bf16.bf16.f32 "
        "{%0,%1,%2,%3}, {%4,%5,%6,%7}, {%8,%9}, {%0,%1,%2,%3};\n"
        : "+f"(c[0]), "+f"(c[1]), "+f"(c[2]), "+f"(c[3])
        : "r"(a[0]), "r"(a[1]), "r"(a[2]), "r"(a[3]), "r"(b[0]), "r"(b[1]));
}

#define CP16(dst, src) \
    asm volatile("cp.async.cg.shared.global [%0], [%1], 16;" :: "r"(dst), "l"(src))
#define CP_COMMIT() asm volatile("cp.async.commit_group;")
#define CP_WAIT(N)  asm volatile("cp.async.wait_group %0;" :: "n"(N))

__device__ __forceinline__ uint32_t pack_hi(float x, float y, float& rx, float& ry) {
    __nv_bfloat162 h;
    h.x = __float2bfloat16(x); h.y = __float2bfloat16(y);
    rx = x - __bfloat162float(h.x);
    ry = y - __bfloat162float(h.y);
    return *(uint32_t*)&h;
}
__device__ __forceinline__ uint32_t pack_bf2(float x, float y) {
    __nv_bfloat162 h;
    h.x = __float2bfloat16(x); h.y = __float2bfloat16(y);
    return *(uint32_t*)&h;
}

// ---------------------------------------------------------------------------
// Merged split kernel: fp32 -> (hi, lo) bf16 planes, float4 vectorized.
// ---------------------------------------------------------------------------
__global__ __launch_bounds__(256) void split_all_kernel(
    const float* __restrict__ x,  const float* __restrict__ Wq,
    const float* __restrict__ Wk, const float* __restrict__ Wv,
    const float* __restrict__ Wo)
{
    const int NX = 1048576;
    const int NW = 262144;
    const int NT = NX + 4 * NW;
    for (int i4 = blockIdx.x * 256 + threadIdx.x; i4 < NT; i4 += gridDim.x * 256) {
        const float* src; __nv_bfloat16 *d0, *d1; int idx;
        if (i4 < NX) { src = x; d0 = g_xs0; d1 = g_xs1; idx = i4; }
        else {
            int r = i4 - NX; int w = r / NW; idx = r - w * NW;
            if (w == 0)      { src = Wq; d0 = g_wb0;           d1 = g_wb1; }
            else if (w == 1) { src = Wk; d0 = g_wb0 + 1048576; d1 = g_wb1 + 1048576; }
            else if (w == 2) { src = Wv; d0 = g_wb0 + 2097152; d1 = g_wb1 + 2097152; }
            else             { src = Wo; d0 = g_wo0;           d1 = g_wo1; }
        }
        float4 a = ((const float4*)src)[idx];
        float r0, r1, r2, r3;
        uint32_t h01 = pack_hi(a.x, a.y, r0, r1);
        uint32_t h23 = pack_hi(a.z, a.w, r2, r3);
        uint32_t l01 = pack_bf2(r0, r1);
        uint32_t l23 = pack_bf2(r2, r3);
        uint2 vh; vh.x = h01; vh.y = h23;
        uint2 vl; vl.x = l01; vl.y = l23;
        *(uint2*)(d0 + 4 * (size_t)idx) = vh;
        *(uint2*)(d1 + 4 * (size_t)idx) = vl;
    }
}

// ---------------------------------------------------------------------------
// QKV projection: 128x96 tile, 384 threads (12 warps, 4m x 3n, warp 32x32).
// grid (32, 32) = 1024 tiles -> 6.92 waves (+1.2% tail).
// Smem/stage 64512: A0@0 A1@18432 (128x144), B0@36864 B1@50688 (96x144).
// q is pre-scaled by 0.125*log2(e) for base-2 softmax.
// ---------------------------------------------------------------------------
#define QKV_SMEM (2*64512)

__global__ __launch_bounds__(384) void qkv_mma_kernel(
    const float* __restrict__ bq, const float* __restrict__ bk,
    const float* __restrict__ bv)
{
    extern __shared__ char smem[];
    const int tid = threadIdx.x;
    const int lane = tid & 31;
    const int wid = tid >> 5;
    const int wr = wid & 3;     // 0..3  (m)
    const int wc = wid >> 2;    // 0..2  (n)
    const int m0 = blockIdx.x * 128;
    const int n0 = blockIdx.y * 96;
    uint32_t sb = smem_u32(smem);

    float acc[2][4][4];
    #pragma unroll
    for (int mt = 0; mt < 2; mt++)
        #pragma unroll
        for (int nt = 0; nt < 4; nt++)
            #pragma unroll
            for (int j = 0; j < 4; j++) acc[mt][nt][j] = 0.f;

    const char* pa0 = (const char*)(g_xs0 + (size_t)m0 * 1024);
    const char* pa1 = (const char*)(g_xs1 + (size_t)m0 * 1024);
    const char* pb0 = (const char*)(g_wb0 + (size_t)n0 * 1024);
    const char* pb1 = (const char*)(g_wb1 + (size_t)n0 * 1024);

    // 2*128*8 + 2*96*8 = 3584 16B-chunks per stage
    auto issue = [&](int ks) {
        uint32_t base = sb + (uint32_t)(ks & 1) * 64512;
        size_t ko = (size_t)ks * 128;
        #pragma unroll
        for (int j = 0; j < 10; j++) {
            int id = j * 384 + tid;
            if (id < 3584) {
                int c = id & 7;
                if (id < 2048) {
                    int plane = id >> 10;
                    int row = (id & 1023) >> 3;
                    const char* s = (plane ? pa1 : pa0) + (size_t)row * 2048 + ko + c * 16;
                    CP16(base + plane * 18432 + row * 144 + c * 16, s);
                } else {
                    int r = id - 2048;
                    int plane = (r >= 768) ? 1 : 0;
                    int row = (plane ? r - 768 : r) >> 3;
                    const char* s = (plane ? pb1 : pb0) + (size_t)row * 2048 + ko + c * 16;
                    CP16(base + 36864 + plane * 13824 + row * 144 + c * 16, s);
                }
            }
        }
    };

    uint32_t aaddr[2];
    #pragma unroll
    for (int mt = 0; mt < 2; mt++)
        aaddr[mt] = sb + (uint32_t)((wr * 32 + mt * 16 + (lane & 15)) * 144 + (lane >> 4) * 16);

    const uint32_t lrow8 = ((lane >> 4) << 3) + (lane & 7);
    const uint32_t khoff = (lane & 8) ? 16u : 0u;
    const uint32_t bgrp = sb + 36864 + (uint32_t)((wc * 32 + lrow8) * 144) + khoff;

    issue(0); CP_COMMIT();

    for (int ks = 0; ks < 16; ks++) {
        CP_WAIT(0);
        __syncthreads();
        if (ks + 1 < 16) { issue(ks + 1); CP_COMMIT(); }

        const uint32_t soff = (uint32_t)(ks & 1) * 64512;
        #pragma unroll
        for (int kc = 0; kc < 4; kc++) {
            const uint32_t ko = soff + kc * 32;
            uint32_t aH[2][4], aL[2][4];
            #pragma unroll
            for (int mt = 0; mt < 2; mt++) {
                ldsm4(aH[mt], aaddr[mt] + ko);
                ldsm4(aL[mt], aaddr[mt] + ko + 18432);
            }
            uint32_t bH01[4], bH23[4], bL01[4], bL23[4];
            ldsm4(bH01, bgrp + ko);
            ldsm4(bH23, bgrp + ko + 2304);
            ldsm4(bL01, bgrp + ko + 13824);
            ldsm4(bL23, bgrp + ko + 13824 + 2304);

            #pragma unroll
            for (int mt = 0; mt < 2; mt++) {
                mma_bf16(acc[mt][0], aH[mt], bH01 + 0);
                mma_bf16(acc[mt][1], aH[mt], bH01 + 2);
                mma_bf16(acc[mt][2], aH[mt], bH23 + 0);
                mma_bf16(acc[mt][3], aH[mt], bH23 + 2);
            }
            #pragma unroll
            for (int mt = 0; mt < 2; mt++) {
                mma_bf16(acc[mt][0], aH[mt], bL01 + 0);
                mma_bf16(acc[mt][1], aH[mt], bL01 + 2);
                mma_bf16(acc[mt][2], aH[mt], bL23 + 0);
                mma_bf16(acc[mt][3], aH[mt], bL23 + 2);
            }
            #pragma unroll
            for (int mt = 0; mt < 2; mt++) {
                mma_bf16(acc[mt][0], aL[mt], bH01 + 0);
                mma_bf16(acc[mt][1], aL[mt], bH01 + 2);
                mma_bf16(acc[mt][2], aL[mt], bH23 + 0);
                mma_bf16(acc[mt][3], aL[mt], bH23 + 2);
            }
        }
    }

    // Epilogue: per-element q/k/v routing (96-tile may straddle boundaries).
    const float L2E = 1.44269504088896340736f;
    #pragma unroll
    for (int mt = 0; mt < 2; mt++) {
        #pragma unroll
        for (int nt = 0; nt < 4; nt++) {
            int fg = n0 + wc * 32 + nt * 8 + (lane & 3) * 2;   // 0..3071
            int which = fg >> 10;
            int f = fg & 1023;
            int h = f >> 6, d = f & 63;
            const float* bias = (which == 0) ? bq : (which == 1) ? bk : bv;
            const float psc = (which == 0) ? 0.125f * L2E : 1.0f;
            float bz0 = bias[f], bz1 = bias[f + 1];
            #pragma unroll
            for (int half = 0; half < 2; half++) {
                int m = m0 + wr * 32 + mt * 16 + (lane >> 2) + half * 8;
                int b = m >> 10, t = m & 1023;
                float v0 = (acc[mt][nt][half * 2 + 0] + bz0) * psc;
                float v1 = (acc[mt][nt][half * 2 + 1] + bz1) * psc;
                __nv_bfloat16 h0 = __float2bfloat16(v0);
                __nv_bfloat16 h1 = __float2bfloat16(v1);
                __nv_bfloat16 l0 = __float2bfloat16(v0 - __bfloat162float(h0));
                __nv_bfloat16 l1 = __float2bfloat16(v1 - __bfloat162float(h1));
                if (which < 2) {
                    size_t idx = (((size_t)(b * 16 + h)) * 1024 + t) * 64 + d;
                    __nv_bfloat162 ph; ph.x = h0; ph.y = h1;
                    __nv_bfloat162 pl; pl.x = l0; pl.y = l1;
                    if (which == 0) {
                        *(__nv_bfloat162*)&g_q0[idx] = ph;
                        *(__nv_bfloat162*)&g_q1[idx] = pl;
                    } else {
                        *(__nv_bfloat162*)&g_k0[idx] = ph;
                        *(__nv_bfloat162*)&g_k1[idx] = pl;
                    }
                } else {
                    size_t base = ((size_t)(b * 16 + h) * 64 + d) * 1024 + t;
                    g_vt0[base] = h0;        g_vt1[base] = l0;
                    g_vt0[base + 1024] = h1; g_vt1[base + 1024] = l1;
                }
            }
        }
    }
}

// ---------------------------------------------------------------------------
// Output projection: 64x64 tile, 256 threads (8 warps, 2m x 4n, warp 32x16).
// grid (64, 16) = 1024 tiles. Smem padded to 120 KB -> 1 CTA/SM (6.92 waves).
// Smem/stage 36864: A0@0 A1@9216 B0@18432 B1@27648 (64x144 each).
// ---------------------------------------------------------------------------
#define OP_SMEM 122880

__global__ __launch_bounds__(256) void outproj_mma_kernel(
    const float* __restrict__ bo, float* __restrict__ out)
{
    extern __shared__ char smem[];
    const int tid = threadIdx.x;
    const int lane = tid & 31;
    const int wid = tid >> 5;
    const int wr = wid & 1;     // 0..1 (m)
    const int wc = wid >> 1;    // 0..3 (n)
    const int m0 = blockIdx.x * 64;
    const int n0 = blockIdx.y * 64;
    uint32_t sb = smem_u32(smem);

    float acc[2][2][4];
    #pragma unroll
    for (int mt = 0; mt < 2; mt++)
        #pragma unroll
        for (int nt = 0; nt < 2; nt++)
            #pragma unroll
            for (int j = 0; j < 4; j++) acc[mt][nt][j] = 0.f;

    const char* planes[4] = {
        (const char*)(g_c0 + (size_t)m0 * 1024), (const char*)(g_c1 + (size_t)m0 * 1024),
        (const char*)(g_wo0 + (size_t)n0 * 1024), (const char*)(g_wo1 + (size_t)n0 * 1024) };

    // 4 planes x 64 rows x 8 chunks = 2048 chunks, 8/thread
    auto issue = [&](int ks) {
        uint32_t base = sb + (uint32_t)(ks & 1) * 36864;
        size_t ko = (size_t)ks * 128;
        #pragma unroll
        for (int j = 0; j < 8; j++) {
            int id = j * 256 + tid;
            int plane = id >> 9;
            int wp = id & 511;
            int row = wp >> 3, c = wp & 7;
            CP16(base + plane * 9216 + row * 144 + c * 16,
                 planes[plane] + (size_t)row * 2048 + ko + c * 16);
        }
    };

    uint32_t aaddr[2];
    #pragma unroll
    for (int mt = 0; mt < 2; mt++)
        aaddr[mt] = sb + (uint32_t)((wr * 32 + mt * 16 + (lane & 15)) * 144 + (lane >> 4) * 16);

    const uint32_t lrow8 = ((lane >> 4) << 3) + (lane & 7);
    const uint32_t khoff = (lane & 8) ? 16u : 0u;
    const uint32_t bgrp = sb + 18432 + (uint32_t)((wc * 16 + lrow8) * 144) + khoff;

    issue(0); CP_COMMIT();

    for (int ks = 0; ks < 16; ks++) {
        CP_WAIT(0);
        __syncthreads();
        if (ks + 1 < 16) { issue(ks + 1); CP_COMMIT(); }

        const uint32_t soff = (uint32_t)(ks & 1) * 36864;
        #pragma unroll
        for (int kc = 0; kc < 4; kc++) {
            const uint32_t ko = soff + kc * 32;
            uint32_t aH[2][4], aL[2][4];
            #pragma unroll
            for (int mt = 0; mt < 2; mt++) {
                ldsm4(aH[mt], aaddr[mt] + ko);
                ldsm4(aL[mt], aaddr[mt] + ko + 9216);
            }
            uint32_t bH[4], bL[4];
            ldsm4(bH, bgrp + ko);
            ldsm4(bL, bgrp + ko + 9216);

            mma_bf16(acc[0][0], aH[0], bH + 0);
            mma_bf16(acc[0][1], aH[0], bH + 2);
            mma_bf16(acc[1][0], aH[1], bH + 0);
            mma_bf16(acc[1][1], aH[1], bH + 2);

            mma_bf16(acc[0][0], aH[0], bL + 0);
            mma_bf16(acc[0][1], aH[0], bL + 2);
            mma_bf16(acc[1][0], aH[1], bL + 0);
            mma_bf16(acc[1][1], aH[1], bL + 2);

            mma_bf16(acc[0][0], aL[0], bH + 0);
            mma_bf16(acc[0][1], aL[0], bH + 2);
            mma_bf16(acc[1][0], aL[1], bH + 0);
            mma_bf16(acc[1][1], aL[1], bH + 2);
        }
    }

    #pragma unroll
    for (int mt = 0; mt < 2; mt++)
        #pragma unroll
        for (int nt = 0; nt < 2; nt++) {
            int f = n0 + wc * 16 + nt * 8 + (lane & 3) * 2;
            float bz0 = bo[f], bz1 = bo[f + 1];
            #pragma unroll
            for (int half = 0; half < 2; half++) {
                int m = m0 + wr * 32 + mt * 16 + (lane >> 2) + half * 8;
                float2 v;
                v.x = acc[mt][nt][half * 2 + 0] + bz0;
                v.y = acc[mt][nt][half * 2 + 1] + bz1;
                *(float2*)&out[(size_t)m * 1024 + f] = v;
            }
        }
}

// ---------------------------------------------------------------------------
// Flash attention, 64-row Q tiles, split-K warp pairs. grid (16, 64),
// 256 threads = 8 warps: pw = wid&3 (q rows pw*16..+16), khalf = wid>>2.
// ---------------------------------------------------------------------------
#define FQ0 0
#define FQ1 9216
#define FKV 36864
#define FKV_STRIDE 71680
#define FK1_OFF 18432
#define FV0_OFF 36864
#define FV1_OFF 54272
#define FL_SMEM (36864 + 2*71680)

__global__ __launch_bounds__(256, 1) void flash_kernel(
    const float* __restrict__ noise, const float* __restrict__ theta)
{
    extern __shared__ char sm[];
    __nv_bfloat16* q0s = (__nv_bfloat16*)(sm + FQ0);
    __nv_bfloat16* q1s = (__nv_bfloat16*)(sm + FQ1);
    uint32_t sb = smem_u32(sm);

    const int tid = threadIdx.x;
    const int lane = tid & 31;
    const int wid = tid >> 5;
    const int pw = wid & 3;
    const int khalf = wid >> 2;
    const int m0 = blockIdx.x * 64;
    const int bh = blockIdx.y;
    const int bb = bh >> 4, hh = bh & 15;

    const char* gk0 = (const char*)(g_k0 + (size_t)bh * 65536);
    const char* gk1 = (const char*)(g_k1 + (size_t)bh * 65536);
    const char* gv0 = (const char*)(g_vt0 + (size_t)bh * 65536);
    const char* gv1 = (const char*)(g_vt1 + (size_t)bh * 65536);

    auto issue = [&](int s0, int b) {
        uint32_t base = sb + FKV + (uint32_t)b * FKV_STRIDE;
        #pragma unroll
        for (int j = 0; j < 4; j++) {
            int idx = j * 256 + tid;       // 0..1023
            int row = idx >> 3, c = idx & 7;
            CP16(base + row * 144 + c * 16,
                 gk0 + (size_t)(s0 + row) * 128 + c * 16);
            CP16(base + FK1_OFF + row * 144 + c * 16,
                 gk1 + (size_t)(s0 + row) * 128 + c * 16);
            int vrow = idx >> 4, vc = idx & 15;
            CP16(base + FV0_OFF + vrow * 272 + vc * 16,
                 gv0 + (size_t)vrow * 2048 + (size_t)s0 * 2 + vc * 16);
            CP16(base + FV1_OFF + vrow * 272 + vc * 16,
                 gv1 + (size_t)vrow * 2048 + (size_t)s0 * 2 + vc * 16);
        }
    };

    issue(0, 0); CP_COMMIT();

    float Tm = 0.f;
    #pragma unroll
    for (int h = 0; h < 16; h++) {
        float sg = 1.f / (1.f + expf(-theta[h]));
        Tm += fabsf(sinf(2.f * sg * 1.57079632679489662f));
    }
    Tm *= (1.f / 16.f);
    const float inv_keep = 1.f / (1.f - Tm + 1e-8f);

    // Load Q tile (64 rows x 64 d, 2 planes)
    {
        const __nv_bfloat16* gq0 = g_q0 + (size_t)bh * 65536 + (size_t)m0 * 64;
        const __nv_bfloat16* gq1 = g_q1 + (size_t)bh * 65536 + (size_t)m0 * 64;
        #pragma unroll
        for (int i = 0; i < 2; i++) {
            int idx = i * 256 + tid;   // 512 chunks per plane
            int row = idx >> 3, c = idx & 7;
            *(float4*)(q0s + row * 72 + c * 8) = *(const float4*)(gq0 + row * 64 + c * 8);
            *(float4*)(q1s + row * 72 + c * 8) = *(const float4*)(gq1 + row * 64 + c * 8);
        }
    }
    __syncthreads();

    uint32_t qH[4][4], qL[4][4];
    {
        uint32_t qa0 = smem_u32(q0s + (pw * 16 + (lane & 15)) * 72 + (lane >> 4) * 8);
        uint32_t qa1 = smem_u32(q1s + (pw * 16 + (lane & 15)) * 72 + (lane >> 4) * 8);
        #pragma unroll
        for (int kc = 0; kc < 4; kc++) {
            ldsm4(qH[kc], qa0 + kc * 32);
            ldsm4(qL[kc], qa1 + kc * 32);
        }
    }

    const uint32_t lrow8 = ((lane >> 4) << 3) + (lane & 7);
    const uint32_t khoff = (lane & 8) ? 16u : 0u;
    const uint32_t kgrp = lrow8 * 144 + khoff + (uint32_t)khalf * 9216;
    const uint32_t vgrp = lrow8 * 272 + khoff + (uint32_t)khalf * 128;

    const int rl = lane >> 2;
    const int row_q = pw * 16 + rl;
    const float* nz_base = noise + (size_t)bh * 1048576
                         + (size_t)(m0 + row_q) * 1024 + khalf * 64 + (lane & 3) * 2;

    float m_prev0 = -1e30f, m_prev1 = -1e30f;
    float l0 = 0.f, l1 = 0.f;
    float O[8][4];
    #pragma unroll
    for (int nt = 0; nt < 8; nt++)
        #pragma unroll
        for (int j = 0; j < 4; j++) O[nt][j] = 0.f;

    for (int it = 0; it < 8; it++) {
        const int s0 = it * 128;
        const int buf = it & 1;
        CP_WAIT(0);
        __syncthreads();
        if (it + 1 < 8) issue(s0 + 128, buf ^ 1);
        CP_COMMIT();

        const uint32_t kbase = sb + FKV + (uint32_t)buf * FKV_STRIDE + kgrp;
        const uint32_t vbase = sb + FKV + (uint32_t)buf * FKV_STRIDE + FV0_OFF + vgrp;

        // ---- scores (16 x 64 for this warp's key half) ----
        float Sa[8][4];
        #pragma unroll
        for (int nt = 0; nt < 8; nt++)
            #pragma unroll
            for (int j = 0; j < 4; j++) Sa[nt][j] = 0.f;

        #pragma unroll
        for (int kc = 0; kc < 4; kc++) {
            #pragma unroll
            for (int ntg = 0; ntg < 4; ntg += 2) {
                uint32_t tH0[4], tL0[4], tH1[4], tL1[4];
                uint32_t a0 = kbase + ntg * 2304 + kc * 32;
                ldsm4(tH0, a0);
                ldsm4(tL0, a0 + FK1_OFF);
                ldsm4(tH1, a0 + 2304);
                ldsm4(tL1, a0 + 2304 + FK1_OFF);
                mma_bf16(Sa[2*ntg],   qH[kc], tH0 + 0);
                mma_bf16(Sa[2*ntg+1], qH[kc], tH0 + 2);
                mma_bf16(Sa[2*ntg+2], qH[kc], tH1 + 0);
                mma_bf16(Sa[2*ntg+3], qH[kc], tH1 + 2);
                mma_bf16(Sa[2*ntg],   qH[kc], tL0 + 0);
                mma_bf16(Sa[2*ntg+1], qH[kc], tL0 + 2);
                mma_bf16(Sa[2*ntg+2], qH[kc], tL1 + 0);
                mma_bf16(Sa[2*ntg+3], qH[kc], tL1 + 2);
                mma_bf16(Sa[2*ntg],   qL[kc], tH0 + 0);
                mma_bf16(Sa[2*ntg+1], qL[kc], tH0 + 2);
                mma_bf16(Sa[2*ntg+2], qL[kc], tH1 + 0);
                mma_bf16(Sa[2*ntg+3], qL[kc], tH1 + 2);
            }
        }

        // ---- per-warp online softmax (base-2) ----
        float mt0 = -1e30f, mt1 = -1e30f;
        #pragma unroll
        for (int nt = 0; nt < 8; nt++) {
            mt0 = fmaxf(mt0, fmaxf(Sa[nt][0], Sa[nt][1]));
            mt1 = fmaxf(mt1, fmaxf(Sa[nt][2], Sa[nt][3]));
        }
        mt0 = fmaxf(mt0, __shfl_xor_sync(0xffffffffu, mt0, 1));
        mt0 = fmaxf(mt0, __shfl_xor_sync(0xffffffffu, mt0, 2));
        mt1 = fmaxf(mt1, __shfl_xor_sync(0xffffffffu, mt1, 1));
        mt1 = fmaxf(mt1, __shfl_xor_sync(0xffffffffu, mt1, 2));

        float mn0 = fmaxf(m_prev0, mt0), mn1 = fmaxf(m_prev1, mt1);
        float f0 = exp2f(m_prev0 - mn0), f1 = exp2f(m_prev1 - mn1);
        m_prev0 = mn0; m_prev1 = mn1;
        l0 *= f0; l1 *= f1;
        #pragma unroll
        for (int nt = 0; nt < 8; nt++) {
            O[nt][0] *= f0; O[nt][1] *= f0;
            O[nt][2] *= f1; O[nt][3] *= f1;
        }

        float rs0 = 0.f, rs1 = 0.f;
        #pragma unroll
        for (int nt = 0; nt < 8; nt++) {
            Sa[nt][0] = exp2f(Sa[nt][0] - mn0);
            Sa[nt][1] = exp2f(Sa[nt][1] - mn0);
            Sa[nt][2] = exp2f(Sa[nt][2] - mn1);
            Sa[nt][3] = exp2f(Sa[nt][3] - mn1);
            rs0 += Sa[nt][0] + Sa[nt][1];
            rs1 += Sa[nt][2] + Sa[nt][3];
        }
        rs0 += __shfl_xor_sync(0xffffffffu, rs0, 1);
        rs0 += __shfl_xor_sync(0xffffffffu, rs0, 2);
        rs1 += __shfl_xor_sync(0xffffffffu, rs1, 1);
        rs1 += __shfl_xor_sync(0xffffffffu, rs1, 2);
        l0 += rs0; l1 += rs1;

        // ---- dropout ----
        const float* nz0 = nz_base + s0;
        #pragma unroll
        for (int nt = 0; nt < 8; nt++) {
            float2 a = *(const float2*)(nz0 + nt * 8);
            float2 b = *(const float2*)(nz0 + 8192 + nt * 8);
            Sa[nt][0] *= (a.x > Tm) ? inv_keep : 0.f;
            Sa[nt][1] *= (a.y > Tm) ? inv_keep : 0.f;
            Sa[nt][2] *= (b.x > Tm) ? inv_keep : 0.f;
            Sa[nt][3] *= (b.y > Tm) ? inv_keep : 0.f;
        }

        // ---- P @ V over this warp's 64 keys ----
        #pragma unroll
        for (int kc = 0; kc < 4; kc++) {
            uint32_t aPH[4], aPL[4];
            float r0, r1;
            aPH[0] = pack_hi(Sa[2*kc][0],   Sa[2*kc][1],   r0, r1);
            aPL[0] = pack_bf2(r0, r1);
            aPH[1] = pack_hi(Sa[2*kc][2],   Sa[2*kc][3],   r0, r1);
            aPL[1] = pack_bf2(r0, r1);
            aPH[2] = pack_hi(Sa[2*kc+1][0], Sa[2*kc+1][1], r0, r1);
            aPL[2] = pack_bf2(r0, r1);
            aPH[3] = pack_hi(Sa[2*kc+1][2], Sa[2*kc+1][3], r0, r1);
            aPL[3] = pack_bf2(r0, r1);
            #pragma unroll
            for (int ntg = 0; ntg < 4; ntg += 2) {
                uint32_t tH0[4], tL0[4], tH1[4], tL1[4];
                uint32_t a0 = vbase + ntg * 4352 + kc * 32;
                ldsm4(tH0, a0);
                ldsm4(tL0, a0 + 17408);
                ldsm4(tH1, a0 + 4352);
                ldsm4(tL1, a0 + 4352 + 17408);
                mma_bf16(O[2*ntg],   aPH, tH0 + 0);
                mma_bf16(O[2*ntg+1], aPH, tH0 + 2);
                mma_bf16(O[2*ntg+2], aPH, tH1 + 0);
                mma_bf16(O[2*ntg+3], aPH, tH1 + 2);
                mma_bf16(O[2*ntg],   aPH, tL0 + 0);
                mma_bf16(O[2*ntg+1], aPH, tL0 + 2);
                mma_bf16(O[2*ntg+2], aPH, tL1 + 0);
                mma_bf16(O[2*ntg+3], aPH, tL1 + 2);
                mma_bf16(O[2*ntg],   aPL, tH0 + 0);
                mma_bf16(O[2*ntg+1], aPL, tH0 + 2);
                mma_bf16(O[2*ntg+2], aPL, tH1 + 0);
                mma_bf16(O[2*ntg+3], aPL, tH1 + 2);
            }
        }
    }

    // ---- merge split-K halves (scratch in dead KV buffer 0) ----
    __syncthreads();
    float* sml = (float*)(sm + FKV);            // [8 warps][16 rows][2] = 1 KB
    float* Osm = (float*)(sm + FKV + 1024);     // [4 pairs][16 rows][64] fp32 = 16 KB

    if ((lane & 3) == 0) {
        sml[(wid * 16 + rl) * 2 + 0]     = m_prev0;
        sml[(wid * 16 + rl) * 2 + 1]     = l0;
        sml[(wid * 16 + rl + 8) * 2 + 0] = m_prev1;
        sml[(wid * 16 + rl + 8) * 2 + 1] = l1;
    }
    __syncthreads();

    const int pwid = wid ^ 4;
    float pm0 = sml[(pwid * 16 + rl) * 2 + 0],     pl0 = sml[(pwid * 16 + rl) * 2 + 1];
    float pm1 = sml[(pwid * 16 + rl + 8) * 2 + 0], pl1 = sml[(pwid * 16 + rl + 8) * 2 + 1];
    float M0 = fmaxf(m_prev0, pm0), M1 = fmaxf(m_prev1, pm1);
    float e0 = exp2f(m_prev0 - M0), e1 = exp2f(m_prev1 - M1);
    float pe0 = exp2f(pm0 - M0),    pe1 = exp2f(pm1 - M1);
    float L0 = l0 * e0 + pl0 * pe0;
    float L1 = l1 * e1 + pl1 * pe1;

    float* Opair = Osm + pw * 1024;
    if (khalf == 1) {
        #pragma unroll
        for (int nt = 0; nt < 8; nt++) {
            int d = nt * 8 + (lane & 3) * 2;
            float2 v0; v0.x = O[nt][0] * e0; v0.y = O[nt][1] * e0;
            float2 v1; v1.x = O[nt][2] * e1; v1.y = O[nt][3] * e1;
            *(float2*)(Opair + rl * 64 + d)       = v0;
            *(float2*)(Opair + (rl + 8) * 64 + d) = v1;
        }
    }
    __syncthreads();

    if (khalf == 0) {
        const float iL0 = 1.f / L0, iL1 = 1.f / L1;
        const int t0 = m0 + row_q;
        #pragma unroll
        for (int nt = 0; nt < 8; nt++) {
            int d = nt * 8 + (lane & 3) * 2;
            float2 ob0 = *(float2*)(Opair + rl * 64 + d);
            float2 ob1 = *(float2*)(Opair + (rl + 8) * 64 + d);
            float v0 = (O[nt][0] * e0 + ob0.x) * iL0;
            float v1 = (O[nt][1] * e0 + ob0.y) * iL0;
            float v2 = (O[nt][2] * e1 + ob1.x) * iL1;
            float v3 = (O[nt][3] * e1 + ob1.y) * iL1;

            __nv_bfloat16 h0 = __float2bfloat16(v0);
            __nv_bfloat16 h1 = __float2bfloat16(v1);
            __nv_bfloat16 lo0 = __float2bfloat16(v0 - __bfloat162float(h0));
            __nv_bfloat16 lo1 = __float2bfloat16(v1 - __bfloat162float(h1));
            size_t idx = ((size_t)bb * 1024 + t0) * 1024 + hh * 64 + d;
            __nv_bfloat162 ph; ph.x = h0; ph.y = h1;
            __nv_bfloat162 pl; pl.x = lo0; pl.y = lo1;
            *(__nv_bfloat162*)&g_c0[idx] = ph;
            *(__nv_bfloat162*)&g_c1[idx] = pl;

            __nv_bfloat16 h2 = __float2bfloat16(v2);
            __nv_bfloat16 h3 = __float2bfloat16(v3);
            __nv_bfloat16 lo2 = __float2bfloat16(v2 - __bfloat162float(h2));
            __nv_bfloat16 lo3 = __float2bfloat16(v3 - __bfloat162float(h3));
            size_t idx2 = ((size_t)bb * 1024 + t0 + 8) * 1024 + hh * 64 + d;
            __nv_bfloat162 ph2; ph2.x = h2; ph2.y = h3;
            __nv_bfloat162 pl2; pl2.x = lo2; pl2.y = lo3;
            *(__nv_bfloat162*)&g_c0[idx2] = ph2;
            *(__nv_bfloat162*)&g_c1[idx2] = pl2;
        }
    }
}

// ---------------------------------------------------------------------------
extern "C" void kernel_launch(void* const* d_in, const int* in_sizes, int n_in,
                              void* d_out, int out_size)
{
    (void)in_sizes; (void)n_in; (void)out_size;
    const float* x     = (const float*)d_in[0];
    const float* noise = (const float*)d_in[1];
    const float* Wq    = (const float*)d_in[2];
    const float* bq    = (const float*)d_in[3];
    const float* Wk    = (const float*)d_in[4];
    const float* bk    = (const float*)d_in[5];
    const float* Wv    = (const float*)d_in[6];
    const float* bv    = (const float*)d_in[7];
    const float* Wo    = (const float*)d_in[8];
    const float* bo    = (const float*)d_in[9];
    const float* theta = (const float*)d_in[10];
    // d_in[11] = corr_w: unused (per-head bias cancels in softmax)
    float* out = (float*)d_out;

    cudaFuncSetAttribute(flash_kernel,
        cudaFuncAttributeMaxDynamicSharedMemorySize, FL_SMEM);
    cudaFuncSetAttribute(qkv_mma_kernel,
        cudaFuncAttributeMaxDynamicSharedMemorySize, QKV_SMEM);
    cudaFuncSetAttribute(outproj_mma_kernel,
        cudaFuncAttributeMaxDynamicSharedMemorySize, OP_SMEM);

    split_all_kernel<<<4096, 256>>>(x, Wq, Wk, Wv, Wo);
    qkv_mma_kernel<<<dim3(32, 32), 384, QKV_SMEM>>>(bq, bk, bv);
    flash_kernel<<<dim3(16, 64), 256, FL_SMEM>>>(noise, theta);
    outproj_mma_kernel<<<dim3(64, 16), 256, OP_SMEM>>>(bo, out);
}

// round 14
// speedup vs baseline: 1.0726x; 1.0726x over previous
#include <cuda_runtime.h>
#include <cuda_bf16.h>
#include <cstdint>
#include <math.h>

// Problem: B=4, H=16, T=1024, D=64, E=1024, M=B*T=4096, BH=64
// GEMMs are TN (C[m,n] = sum_k A[m,k]*B[n,k]) on bf16x2 split planes.

// ---------------------------------------------------------------------------
// Device-global scratch
// ---------------------------------------------------------------------------
__device__ __nv_bfloat16 g_xs0[4194304], g_xs1[4194304];   // x split   [4096][1024]
__device__ __nv_bfloat16 g_wb0[3145728], g_wb1[3145728];   // Wq|Wk|Wv  [3072][1024]
__device__ __nv_bfloat16 g_wo0[1048576], g_wo1[1048576];   // Wo        [1024][1024]
__device__ __nv_bfloat16 g_q0[4194304],  g_q1[4194304];    // q (scaled 0.125*log2e) [bh][t][d]
__device__ __nv_bfloat16 g_k0[4194304],  g_k1[4194304];    // k  [bh][s][d]
__device__ __nv_bfloat16 g_vt0[4194304], g_vt1[4194304];   // vT [bh][d][s]
__device__ __nv_bfloat16 g_c0[4194304],  g_c1[4194304];    // ctx planes [m][e]

// ---------------------------------------------------------------------------
// PTX helpers
// ---------------------------------------------------------------------------
__device__ __forceinline__ uint32_t smem_u32(const void* p) {
    uint32_t a;
    asm("{ .reg .u64 t; cvta.to.shared.u64 t, %1; cvt.u32.u64 %0, t; }" : "=r"(a) : "l"(p));
    return a;
}

__device__ __forceinline__ void ldsm4(uint32_t r[4], uint32_t addr) {
    asm volatile("ldmatrix.sync.aligned.m8n8.x4.shared.b16 {%0,%1,%2,%3}, [%4];"
        : "=r"(r[0]), "=r"(r[1]), "=r"(r[2]), "=r"(r[3]) : "r"(addr));
}

__device__ __forceinline__ void mma_bf16(float* c, const uint32_t* a, const uint32_t* b) {
    asm volatile(
        "mma.sync.aligned.m16n8k16.row.col.f32.bf16.bf16.f32 "
        "{%0,%1,%2,%3}, {%4,%5,%6,%7}, {%8,%9}, {%0,%1,%2,%3};\n"
        : "+f"(c[0]), "+f"(c[1]), "+f"(c[2]), "+f"(c[3])
        : "r"(a[0]), "r"(a[1]), "r"(a[2]), "r"(a[3]), "r"(b[0]), "r"(b[1]));
}

#define CP16(dst, src) \
    asm volatile("cp.async.cg.shared.global [%0], [%1], 16;" :: "r"(dst), "l"(src))
#define CP_COMMIT() asm volatile("cp.async.commit_group;")
#define CP_WAIT(N)  asm volatile("cp.async.wait_group %0;" :: "n"(N))

__device__ __forceinline__ uint32_t pack_hi(float x, float y, float& rx, float& ry) {
    __nv_bfloat162 h;
    h.x = __float2bfloat16(x); h.y = __float2bfloat16(y);
    rx = x - __bfloat162float(h.x);
    ry = y - __bfloat162float(h.y);
    return *(uint32_t*)&h;
}
__device__ __forceinline__ uint32_t pack_bf2(float x, float y) {
    __nv_bfloat162 h;
    h.x = __float2bfloat16(x); h.y = __float2bfloat16(y);
    return *(uint32_t*)&h;
}

// ---------------------------------------------------------------------------
// Merged split kernel: fp32 -> (hi, lo) bf16 planes, float4 vectorized.
// ---------------------------------------------------------------------------
__global__ __launch_bounds__(256) void split_all_kernel(
    const float* __restrict__ x,  const float* __restrict__ Wq,
    const float* __restrict__ Wk, const float* __restrict__ Wv,
    const float* __restrict__ Wo)
{
    const int NX = 1048576;
    const int NW = 262144;
    const int NT = NX + 4 * NW;
    for (int i4 = blockIdx.x * 256 + threadIdx.x; i4 < NT; i4 += gridDim.x * 256) {
        const float* src; __nv_bfloat16 *d0, *d1; int idx;
        if (i4 < NX) { src = x; d0 = g_xs0; d1 = g_xs1; idx = i4; }
        else {
            int r = i4 - NX; int w = r / NW; idx = r - w * NW;
            if (w == 0)      { src = Wq; d0 = g_wb0;           d1 = g_wb1; }
            else if (w == 1) { src = Wk; d0 = g_wb0 + 1048576; d1 = g_wb1 + 1048576; }
            else if (w == 2) { src = Wv; d0 = g_wb0 + 2097152; d1 = g_wb1 + 2097152; }
            else             { src = Wo; d0 = g_wo0;           d1 = g_wo1; }
        }
        float4 a = ((const float4*)src)[idx];
        float r0, r1, r2, r3;
        uint32_t h01 = pack_hi(a.x, a.y, r0, r1);
        uint32_t h23 = pack_hi(a.z, a.w, r2, r3);
        uint32_t l01 = pack_bf2(r0, r1);
        uint32_t l23 = pack_bf2(r2, r3);
        uint2 vh; vh.x = h01; vh.y = h23;
        uint2 vl; vl.x = l01; vl.y = l23;
        *(uint2*)(d0 + 4 * (size_t)idx) = vh;
        *(uint2*)(d1 + 4 * (size_t)idx) = vl;
    }
}

// ---------------------------------------------------------------------------
// Core 128x128 tile GEMM (TN), bf16x2 3-pass, fp32 acc. (R12 shape — best)
// 512 threads = 16 warps as 4(m) x 4(n); warp tile 32x32.
// BK=64, 2-stage cp.async double buffer; pass-major MMA order.
// ---------------------------------------------------------------------------
#define GP_SMEM 147456

template<int KSTEPS, int LDA, int LDB>
__device__ __forceinline__ void gemm128_pipe(
    char* smem,
    const __nv_bfloat16* __restrict__ A0, const __nv_bfloat16* __restrict__ A1,
    const __nv_bfloat16* __restrict__ B0, const __nv_bfloat16* __restrict__ B1,
    float acc[2][4][4])
{
    const int tid = threadIdx.x;
    const int lane = tid & 31;
    const int wid = tid >> 5;
    const int wr = wid >> 2;
    const int wc = wid & 3;
    uint32_t sb = smem_u32(smem);

    #pragma unroll
    for (int mt = 0; mt < 2; mt++)
        #pragma unroll
        for (int nt = 0; nt < 4; nt++)
            #pragma unroll
            for (int j = 0; j < 4; j++) acc[mt][nt][j] = 0.f;

    const char* planes[4] = {
        (const char*)A0, (const char*)A1, (const char*)B0, (const char*)B1 };
    const int lds[4] = { LDA, LDA, LDB, LDB };

    auto issue = [&](int ks) {
        uint32_t base = sb + (uint32_t)(ks & 1) * 73728;
        #pragma unroll
        for (int j = 0; j < 8; j++) {
            int id = j * 512 + tid;
            int plane = id >> 10;
            int wp = id & 1023;
            int row = wp >> 3, c = wp & 7;
            CP16(base + plane * 18432 + row * 144 + c * 16,
                 planes[plane] + (size_t)row * (lds[plane] * 2) + (size_t)ks * 128 + c * 16);
        }
    };

    uint32_t aaddr[2];
    #pragma unroll
    for (int mt = 0; mt < 2; mt++)
        aaddr[mt] = sb + (uint32_t)((wr * 32 + mt * 16 + (lane & 15)) * 144 + (lane >> 4) * 16);

    const uint32_t bgrp = sb + 36864
        + (uint32_t)((wc * 32 + ((lane >> 4) << 3) + (lane & 7)) * 144)
        + ((lane & 8) ? 16u : 0u);

    issue(0); CP_COMMIT();

    for (int ks = 0; ks < KSTEPS; ks++) {
        CP_WAIT(0);
        __syncthreads();
        if (ks + 1 < KSTEPS) { issue(ks + 1); CP_COMMIT(); }

        const uint32_t soff = (uint32_t)(ks & 1) * 73728;
        #pragma unroll
        for (int kc = 0; kc < 4; kc++) {
            const uint32_t ko = soff + kc * 32;
            uint32_t aH[2][4], aL[2][4];
            #pragma unroll
            for (int mt = 0; mt < 2; mt++) {
                ldsm4(aH[mt], aaddr[mt] + ko);
                ldsm4(aL[mt], aaddr[mt] + ko + 18432);
            }
            uint32_t bH01[4], bH23[4], bL01[4], bL23[4];
            ldsm4(bH01, bgrp + ko);
            ldsm4(bH23, bgrp + ko + 2304);
            ldsm4(bL01, bgrp + ko + 18432);
            ldsm4(bL23, bgrp + ko + 18432 + 2304);

            #pragma unroll
            for (int mt = 0; mt < 2; mt++) {
                mma_bf16(acc[mt][0], aH[mt], bH01 + 0);
                mma_bf16(acc[mt][1], aH[mt], bH01 + 2);
                mma_bf16(acc[mt][2], aH[mt], bH23 + 0);
                mma_bf16(acc[mt][3], aH[mt], bH23 + 2);
            }
            #pragma unroll
            for (int mt = 0; mt < 2; mt++) {
                mma_bf16(acc[mt][0], aH[mt], bL01 + 0);
                mma_bf16(acc[mt][1], aH[mt], bL01 + 2);
                mma_bf16(acc[mt][2], aH[mt], bL23 + 0);
                mma_bf16(acc[mt][3], aH[mt], bL23 + 2);
            }
            #pragma unroll
            for (int mt = 0; mt < 2; mt++) {
                mma_bf16(acc[mt][0], aL[mt], bH01 + 0);
                mma_bf16(acc[mt][1], aL[mt], bH01 + 2);
                mma_bf16(acc[mt][2], aL[mt], bH23 + 0);
                mma_bf16(acc[mt][3], aL[mt], bH23 + 2);
            }
        }
    }
}

// ---------------------------------------------------------------------------
// QKV projection. grid (32, 24), 512 threads.
// q is pre-scaled by 0.125 * log2(e): softmax runs in base-2 domain.
// ---------------------------------------------------------------------------
__global__ __launch_bounds__(512) void qkv_mma_kernel(
    const float* __restrict__ bq, const float* __restrict__ bk,
    const float* __restrict__ bv)
{
    extern __shared__ char smem[];
    const int m0 = blockIdx.x * 128;
    const int n0 = blockIdx.y * 128;
    float acc[2][4][4];
    gemm128_pipe<16, 1024, 1024>(smem,
        g_xs0 + (size_t)m0 * 1024, g_xs1 + (size_t)m0 * 1024,
        g_wb0 + (size_t)n0 * 1024, g_wb1 + (size_t)n0 * 1024, acc);

    const int which = n0 >> 10;
    const int fbase = n0 & 1023;
    const float* bias = (which == 0) ? bq : (which == 1) ? bk : bv;
    const float psc = (which == 0) ? 0.125f * 1.44269504088896340736f : 1.0f;

    const int tid = threadIdx.x, lane = tid & 31, wid = tid >> 5;
    const int wr = wid >> 2, wc = wid & 3;

    #pragma unroll
    for (int mt = 0; mt < 2; mt++) {
        #pragma unroll
        for (int nt = 0; nt < 4; nt++) {
            int f = fbase + wc * 32 + nt * 8 + (lane & 3) * 2;
            int h = f >> 6, d = f & 63;
            float bz0 = bias[f], bz1 = bias[f + 1];
            #pragma unroll
            for (int half = 0; half < 2; half++) {
                int m = m0 + wr * 32 + mt * 16 + (lane >> 2) + half * 8;
                int b = m >> 10, t = m & 1023;
                float v0 = (acc[mt][nt][half * 2 + 0] + bz0) * psc;
                float v1 = (acc[mt][nt][half * 2 + 1] + bz1) * psc;
                __nv_bfloat16 h0 = __float2bfloat16(v0);
                __nv_bfloat16 h1 = __float2bfloat16(v1);
                __nv_bfloat16 l0 = __float2bfloat16(v0 - __bfloat162float(h0));
                __nv_bfloat16 l1 = __float2bfloat16(v1 - __bfloat162float(h1));
                if (which < 2) {
                    size_t idx = (((size_t)(b * 16 + h)) * 1024 + t) * 64 + d;
                    __nv_bfloat162 ph; ph.x = h0; ph.y = h1;
                    __nv_bfloat162 pl; pl.x = l0; pl.y = l1;
                    if (which == 0) {
                        *(__nv_bfloat162*)&g_q0[idx] = ph;
                        *(__nv_bfloat162*)&g_q1[idx] = pl;
                    } else {
                        *(__nv_bfloat162*)&g_k0[idx] = ph;
                        *(__nv_bfloat162*)&g_k1[idx] = pl;
                    }
                } else {
                    size_t base = ((size_t)(b * 16 + h) * 64 + d) * 1024 + t;
                    g_vt0[base] = h0;        g_vt1[base] = l0;
                    g_vt0[base + 1024] = h1; g_vt1[base + 1024] = l1;
                }
            }
        }
    }
}

// ---------------------------------------------------------------------------
// Flash attention, 64-row Q tiles, split-K warp pairs. grid (16, 64),
// 256 threads = 8 warps: pw = wid&3 (q rows pw*16..+16), khalf = wid>>2.
// 1024 tiles -> 6.92 waves (1.2% tail). (R13's flash — the piece that won.)
// ---------------------------------------------------------------------------
#define FQ0 0
#define FQ1 9216
#define FKV 36864
#define FKV_STRIDE 71680
#define FK1_OFF 18432
#define FV0_OFF 36864
#define FV1_OFF 54272
#define FL_SMEM (36864 + 2*71680)

__global__ __launch_bounds__(256, 1) void flash_kernel(
    const float* __restrict__ noise, const float* __restrict__ theta)
{
    extern __shared__ char sm[];
    __nv_bfloat16* q0s = (__nv_bfloat16*)(sm + FQ0);
    __nv_bfloat16* q1s = (__nv_bfloat16*)(sm + FQ1);
    uint32_t sb = smem_u32(sm);

    const int tid = threadIdx.x;
    const int lane = tid & 31;
    const int wid = tid >> 5;
    const int pw = wid & 3;
    const int khalf = wid >> 2;
    const int m0 = blockIdx.x * 64;
    const int bh = blockIdx.y;
    const int bb = bh >> 4, hh = bh & 15;

    const char* gk0 = (const char*)(g_k0 + (size_t)bh * 65536);
    const char* gk1 = (const char*)(g_k1 + (size_t)bh * 65536);
    const char* gv0 = (const char*)(g_vt0 + (size_t)bh * 65536);
    const char* gv1 = (const char*)(g_vt1 + (size_t)bh * 65536);

    auto issue = [&](int s0, int b) {
        uint32_t base = sb + FKV + (uint32_t)b * FKV_STRIDE;
        #pragma unroll
        for (int j = 0; j < 4; j++) {
            int idx = j * 256 + tid;       // 0..1023
            int row = idx >> 3, c = idx & 7;
            CP16(base + row * 144 + c * 16,
                 gk0 + (size_t)(s0 + row) * 128 + c * 16);
            CP16(base + FK1_OFF + row * 144 + c * 16,
                 gk1 + (size_t)(s0 + row) * 128 + c * 16);
            int vrow = idx >> 4, vc = idx & 15;
            CP16(base + FV0_OFF + vrow * 272 + vc * 16,
                 gv0 + (size_t)vrow * 2048 + (size_t)s0 * 2 + vc * 16);
            CP16(base + FV1_OFF + vrow * 272 + vc * 16,
                 gv1 + (size_t)vrow * 2048 + (size_t)s0 * 2 + vc * 16);
        }
    };

    issue(0, 0); CP_COMMIT();

    float Tm = 0.f;
    #pragma unroll
    for (int h = 0; h < 16; h++) {
        float sg = 1.f / (1.f + expf(-theta[h]));
        Tm += fabsf(sinf(2.f * sg * 1.57079632679489662f));
    }
    Tm *= (1.f / 16.f);
    const float inv_keep = 1.f / (1.f - Tm + 1e-8f);

    // Load Q tile (64 rows x 64 d, 2 planes)
    {
        const __nv_bfloat16* gq0 = g_q0 + (size_t)bh * 65536 + (size_t)m0 * 64;
        const __nv_bfloat16* gq1 = g_q1 + (size_t)bh * 65536 + (size_t)m0 * 64;
        #pragma unroll
        for (int i = 0; i < 2; i++) {
            int idx = i * 256 + tid;
            int row = idx >> 3, c = idx & 7;
            *(float4*)(q0s + row * 72 + c * 8) = *(const float4*)(gq0 + row * 64 + c * 8);
            *(float4*)(q1s + row * 72 + c * 8) = *(const float4*)(gq1 + row * 64 + c * 8);
        }
    }
    __syncthreads();

    uint32_t qH[4][4], qL[4][4];
    {
        uint32_t qa0 = smem_u32(q0s + (pw * 16 + (lane & 15)) * 72 + (lane >> 4) * 8);
        uint32_t qa1 = smem_u32(q1s + (pw * 16 + (lane & 15)) * 72 + (lane >> 4) * 8);
        #pragma unroll
        for (int kc = 0; kc < 4; kc++) {
            ldsm4(qH[kc], qa0 + kc * 32);
            ldsm4(qL[kc], qa1 + kc * 32);
        }
    }

    const uint32_t lrow8 = ((lane >> 4) << 3) + (lane & 7);
    const uint32_t khoff = (lane & 8) ? 16u : 0u;
    const uint32_t kgrp = lrow8 * 144 + khoff + (uint32_t)khalf * 9216;
    const uint32_t vgrp = lrow8 * 272 + khoff + (uint32_t)khalf * 128;

    const int rl = lane >> 2;
    const int row_q = pw * 16 + rl;
    const float* nz_base = noise + (size_t)bh * 1048576
                         + (size_t)(m0 + row_q) * 1024 + khalf * 64 + (lane & 3) * 2;

    float m_prev0 = -1e30f, m_prev1 = -1e30f;
    float l0 = 0.f, l1 = 0.f;
    float O[8][4];
    #pragma unroll
    for (int nt = 0; nt < 8; nt++)
        #pragma unroll
        for (int j = 0; j < 4; j++) O[nt][j] = 0.f;

    for (int it = 0; it < 8; it++) {
        const int s0 = it * 128;
        const int buf = it & 1;
        CP_WAIT(0);
        __syncthreads();
        if (it + 1 < 8) issue(s0 + 128, buf ^ 1);
        CP_COMMIT();

        const uint32_t kbase = sb + FKV + (uint32_t)buf * FKV_STRIDE + kgrp;
        const uint32_t vbase = sb + FKV + (uint32_t)buf * FKV_STRIDE + FV0_OFF + vgrp;

        // ---- scores (16 x 64 for this warp's key half) ----
        float Sa[8][4];
        #pragma unroll
        for (int nt = 0; nt < 8; nt++)
            #pragma unroll
            for (int j = 0; j < 4; j++) Sa[nt][j] = 0.f;

        #pragma unroll
        for (int kc = 0; kc < 4; kc++) {
            #pragma unroll
            for (int ntg = 0; ntg < 4; ntg += 2) {
                uint32_t tH0[4], tL0[4], tH1[4], tL1[4];
                uint32_t a0 = kbase + ntg * 2304 + kc * 32;
                ldsm4(tH0, a0);
                ldsm4(tL0, a0 + FK1_OFF);
                ldsm4(tH1, a0 + 2304);
                ldsm4(tL1, a0 + 2304 + FK1_OFF);
                mma_bf16(Sa[2*ntg],   qH[kc], tH0 + 0);
                mma_bf16(Sa[2*ntg+1], qH[kc], tH0 + 2);
                mma_bf16(Sa[2*ntg+2], qH[kc], tH1 + 0);
                mma_bf16(Sa[2*ntg+3], qH[kc], tH1 + 2);
                mma_bf16(Sa[2*ntg],   qH[kc], tL0 + 0);
                mma_bf16(Sa[2*ntg+1], qH[kc], tL0 + 2);
                mma_bf16(Sa[2*ntg+2], qH[kc], tL1 + 0);
                mma_bf16(Sa[2*ntg+3], qH[kc], tL1 + 2);
                mma_bf16(Sa[2*ntg],   qL[kc], tH0 + 0);
                mma_bf16(Sa[2*ntg+1], qL[kc], tH0 + 2);
                mma_bf16(Sa[2*ntg+2], qL[kc], tH1 + 0);
                mma_bf16(Sa[2*ntg+3], qL[kc], tH1 + 2);
            }
        }

        // ---- per-warp online softmax (base-2) ----
        float mt0 = -1e30f, mt1 = -1e30f;
        #pragma unroll
        for (int nt = 0; nt < 8; nt++) {
            mt0 = fmaxf(mt0, fmaxf(Sa[nt][0], Sa[nt][1]));
            mt1 = fmaxf(mt1, fmaxf(Sa[nt][2], Sa[nt][3]));
        }
        mt0 = fmaxf(mt0, __shfl_xor_sync(0xffffffffu, mt0, 1));
        mt0 = fmaxf(mt0, __shfl_xor_sync(0xffffffffu, mt0, 2));
        mt1 = fmaxf(mt1, __shfl_xor_sync(0xffffffffu, mt1, 1));
        mt1 = fmaxf(mt1, __shfl_xor_sync(0xffffffffu, mt1, 2));

        float mn0 = fmaxf(m_prev0, mt0), mn1 = fmaxf(m_prev1, mt1);
        float f0 = exp2f(m_prev0 - mn0), f1 = exp2f(m_prev1 - mn1);
        m_prev0 = mn0; m_prev1 = mn1;
        l0 *= f0; l1 *= f1;
        #pragma unroll
        for (int nt = 0; nt < 8; nt++) {
            O[nt][0] *= f0; O[nt][1] *= f0;
            O[nt][2] *= f1; O[nt][3] *= f1;
        }

        float rs0 = 0.f, rs1 = 0.f;
        #pragma unroll
        for (int nt = 0; nt < 8; nt++) {
            Sa[nt][0] = exp2f(Sa[nt][0] - mn0);
            Sa[nt][1] = exp2f(Sa[nt][1] - mn0);
            Sa[nt][2] = exp2f(Sa[nt][2] - mn1);
            Sa[nt][3] = exp2f(Sa[nt][3] - mn1);
            rs0 += Sa[nt][0] + Sa[nt][1];
            rs1 += Sa[nt][2] + Sa[nt][3];
        }
        rs0 += __shfl_xor_sync(0xffffffffu, rs0, 1);
        rs0 += __shfl_xor_sync(0xffffffffu, rs0, 2);
        rs1 += __shfl_xor_sync(0xffffffffu, rs1, 1);
        rs1 += __shfl_xor_sync(0xffffffffu, rs1, 2);
        l0 += rs0; l1 += rs1;

        // ---- dropout ----
        const float* nz0 = nz_base + s0;
        #pragma unroll
        for (int nt = 0; nt < 8; nt++) {
            float2 a = *(const float2*)(nz0 + nt * 8);
            float2 b = *(const float2*)(nz0 + 8192 + nt * 8);
            Sa[nt][0] *= (a.x > Tm) ? inv_keep : 0.f;
            Sa[nt][1] *= (a.y > Tm) ? inv_keep : 0.f;
            Sa[nt][2] *= (b.x > Tm) ? inv_keep : 0.f;
            Sa[nt][3] *= (b.y > Tm) ? inv_keep : 0.f;
        }

        // ---- P @ V over this warp's 64 keys ----
        #pragma unroll
        for (int kc = 0; kc < 4; kc++) {
            uint32_t aPH[4], aPL[4];
            float r0, r1;
            aPH[0] = pack_hi(Sa[2*kc][0],   Sa[2*kc][1],   r0, r1);
            aPL[0] = pack_bf2(r0, r1);
            aPH[1] = pack_hi(Sa[2*kc][2],   Sa[2*kc][3],   r0, r1);
            aPL[1] = pack_bf2(r0, r1);
            aPH[2] = pack_hi(Sa[2*kc+1][0], Sa[2*kc+1][1], r0, r1);
            aPL[2] = pack_bf2(r0, r1);
            aPH[3] = pack_hi(Sa[2*kc+1][2], Sa[2*kc+1][3], r0, r1);
            aPL[3] = pack_bf2(r0, r1);
            #pragma unroll
            for (int ntg = 0; ntg < 4; ntg += 2) {
                uint32_t tH0[4], tL0[4], tH1[4], tL1[4];
                uint32_t a0 = vbase + ntg * 4352 + kc * 32;
                ldsm4(tH0, a0);
                ldsm4(tL0, a0 + 17408);
                ldsm4(tH1, a0 + 4352);
                ldsm4(tL1, a0 + 4352 + 17408);
                mma_bf16(O[2*ntg],   aPH, tH0 + 0);
                mma_bf16(O[2*ntg+1], aPH, tH0 + 2);
                mma_bf16(O[2*ntg+2], aPH, tH1 + 0);
                mma_bf16(O[2*ntg+3], aPH, tH1 + 2);
                mma_bf16(O[2*ntg],   aPH, tL0 + 0);
                mma_bf16(O[2*ntg+1], aPH, tL0 + 2);
                mma_bf16(O[2*ntg+2], aPH, tL1 + 0);
                mma_bf16(O[2*ntg+3], aPH, tL1 + 2);
                mma_bf16(O[2*ntg],   aPL, tH0 + 0);
                mma_bf16(O[2*ntg+1], aPL, tH0 + 2);
                mma_bf16(O[2*ntg+2], aPL, tH1 + 0);
                mma_bf16(O[2*ntg+3], aPL, tH1 + 2);
            }
        }
    }

    // ---- merge split-K halves (scratch in dead KV buffer 0) ----
    __syncthreads();
    float* sml = (float*)(sm + FKV);            // [8 warps][16 rows][2] = 1 KB
    float* Osm = (float*)(sm + FKV + 1024);     // [4 pairs][16 rows][64] fp32 = 16 KB

    if ((lane & 3) == 0) {
        sml[(wid * 16 + rl) * 2 + 0]     = m_prev0;
        sml[(wid * 16 + rl) * 2 + 1]     = l0;
        sml[(wid * 16 + rl + 8) * 2 + 0] = m_prev1;
        sml[(wid * 16 + rl + 8) * 2 + 1] = l1;
    }
    __syncthreads();

    const int pwid = wid ^ 4;
    float pm0 = sml[(pwid * 16 + rl) * 2 + 0],     pl0 = sml[(pwid * 16 + rl) * 2 + 1];
    float pm1 = sml[(pwid * 16 + rl + 8) * 2 + 0], pl1 = sml[(pwid * 16 + rl + 8) * 2 + 1];
    float M0 = fmaxf(m_prev0, pm0), M1 = fmaxf(m_prev1, pm1);
    float e0 = exp2f(m_prev0 - M0), e1 = exp2f(m_prev1 - M1);
    float pe0 = exp2f(pm0 - M0),    pe1 = exp2f(pm1 - M1);
    float L0 = l0 * e0 + pl0 * pe0;
    float L1 = l1 * e1 + pl1 * pe1;

    float* Opair = Osm + pw * 1024;
    if (khalf == 1) {
        #pragma unroll
        for (int nt = 0; nt < 8; nt++) {
            int d = nt * 8 + (lane & 3) * 2;
            float2 v0; v0.x = O[nt][0] * e0; v0.y = O[nt][1] * e0;
            float2 v1; v1.x = O[nt][2] * e1; v1.y = O[nt][3] * e1;
            *(float2*)(Opair + rl * 64 + d)       = v0;
            *(float2*)(Opair + (rl + 8) * 64 + d) = v1;
        }
    }
    __syncthreads();

    if (khalf == 0) {
        const float iL0 = 1.f / L0, iL1 = 1.f / L1;
        const int t0 = m0 + row_q;
        #pragma unroll
        for (int nt = 0; nt < 8; nt++) {
            int d = nt * 8 + (lane & 3) * 2;
            float2 ob0 = *(float2*)(Opair + rl * 64 + d);
            float2 ob1 = *(float2*)(Opair + (rl + 8) * 64 + d);
            float v0 = (O[nt][0] * e0 + ob0.x) * iL0;
            float v1 = (O[nt][1] * e0 + ob0.y) * iL0;
            float v2 = (O[nt][2] * e1 + ob1.x) * iL1;
            float v3 = (O[nt][3] * e1 + ob1.y) * iL1;

            __nv_bfloat16 h0 = __float2bfloat16(v0);
            __nv_bfloat16 h1 = __float2bfloat16(v1);
            __nv_bfloat16 lo0 = __float2bfloat16(v0 - __bfloat162float(h0));
            __nv_bfloat16 lo1 = __float2bfloat16(v1 - __bfloat162float(h1));
            size_t idx = ((size_t)bb * 1024 + t0) * 1024 + hh * 64 + d;
            __nv_bfloat162 ph; ph.x = h0; ph.y = h1;
            __nv_bfloat162 pl; pl.x = lo0; pl.y = lo1;
            *(__nv_bfloat162*)&g_c0[idx] = ph;
            *(__nv_bfloat162*)&g_c1[idx] = pl;

            __nv_bfloat16 h2 = __float2bfloat16(v2);
            __nv_bfloat16 h3 = __float2bfloat16(v3);
            __nv_bfloat16 lo2 = __float2bfloat16(v2 - __bfloat162float(h2));
            __nv_bfloat16 lo3 = __float2bfloat16(v3 - __bfloat162float(h3));
            size_t idx2 = ((size_t)bb * 1024 + t0 + 8) * 1024 + hh * 64 + d;
            __nv_bfloat162 ph2; ph2.x = h2; ph2.y = h3;
            __nv_bfloat162 pl2; pl2.x = lo2; pl2.y = lo3;
            *(__nv_bfloat162*)&g_c0[idx2] = ph2;
            *(__nv_bfloat162*)&g_c1[idx2] = pl2;
        }
    }
}

// ---------------------------------------------------------------------------
// Output projection. grid (32, 8), 512 threads. out = ctx @ Wo^T + bo.
// ---------------------------------------------------------------------------
__global__ __launch_bounds__(512) void outproj_mma_kernel(
    const float* __restrict__ bo, float* __restrict__ out)
{
    extern __shared__ char smem[];
    const int m0 = blockIdx.x * 128;
    const int n0 = blockIdx.y * 128;
    float acc[2][4][4];
    gemm128_pipe<16, 1024, 1024>(smem,
        g_c0 + (size_t)m0 * 1024, g_c1 + (size_t)m0 * 1024,
        g_wo0 + (size_t)n0 * 1024, g_wo1 + (size_t)n0 * 1024, acc);

    const int tid = threadIdx.x, lane = tid & 31, wid = tid >> 5;
    const int wr = wid >> 2, wc = wid & 3;

    #pragma unroll
    for (int mt = 0; mt < 2; mt++)
        #pragma unroll
        for (int nt = 0; nt < 4; nt++) {
            int f = n0 + wc * 32 + nt * 8 + (lane & 3) * 2;
            float bz0 = bo[f], bz1 = bo[f + 1];
            #pragma unroll
            for (int half = 0; half < 2; half++) {
                int m = m0 + wr * 32 + mt * 16 + (lane >> 2) + half * 8;
                float2 v;
                v.x = acc[mt][nt][half * 2 + 0] + bz0;
                v.y = acc[mt][nt][half * 2 + 1] + bz1;
                *(float2*)&out[(size_t)m * 1024 + f] = v;
            }
        }
}

// ---------------------------------------------------------------------------
extern "C" void kernel_launch(void* const* d_in, const int* in_sizes, int n_in,
                              void* d_out, int out_size)
{
    (void)in_sizes; (void)n_in; (void)out_size;
    const float* x     = (const float*)d_in[0];
    const float* noise = (const float*)d_in[1];
    const float* Wq    = (const float*)d_in[2];
    const float* bq    = (const float*)d_in[3];
    const float* Wk    = (const float*)d_in[4];
    const float* bk    = (const float*)d_in[5];
    const float* Wv    = (const float*)d_in[6];
    const float* bv    = (const float*)d_in[7];
    const float* Wo    = (const float*)d_in[8];
    const float* bo    = (const float*)d_in[9];
    const float* theta = (const float*)d_in[10];
    // d_in[11] = corr_w: unused (per-head bias cancels in softmax)
    float* out = (float*)d_out;

    cudaFuncSetAttribute(flash_kernel,
        cudaFuncAttributeMaxDynamicSharedMemorySize, FL_SMEM);
    cudaFuncSetAttribute(qkv_mma_kernel,
        cudaFuncAttributeMaxDynamicSharedMemorySize, GP_SMEM);
    cudaFuncSetAttribute(outproj_mma_kernel,
        cudaFuncAttributeMaxDynamicSharedMemorySize, GP_SMEM);

    split_all_kernel<<<4096, 256>>>(x, Wq, Wk, Wv, Wo);
    qkv_mma_kernel<<<dim3(32, 24), 512, GP_SMEM>>>(bq, bk, bv);
    flash_kernel<<<dim3(16, 64), 256, FL_SMEM>>>(noise, theta);
    outproj_mma_kernel<<<dim3(32, 8), 512, GP_SMEM>>>(bo, out);
}

// round 15
// speedup vs baseline: 1.2371x; 1.1534x over previous
#include <cuda_runtime.h>
#include <cuda_fp16.h>
#include <cstdint>
#include <math.h>

// Problem: B=4, H=16, T=1024, D=64, E=1024, M=B*T=4096, BH=64
// fp16x2 split GEMMs. qkv: 3-pass (exact to eps^2). scores/PV/outproj: 2-pass.

// ---------------------------------------------------------------------------
// Device-global scratch (fp16)
// ---------------------------------------------------------------------------
__device__ __half g_xs0[4194304], g_xs1[4194304];   // x split   [4096][1024]
__device__ __half g_wb0[3145728], g_wb1[3145728];   // Wq|Wk|Wv  [3072][1024]
__device__ __half g_wo0[1048576];                   // Wo single plane
__device__ __half g_q0[4194304],  g_q1[4194304];    // q (scaled 0.125*log2e) 2-plane
__device__ __half g_k0[4194304];                    // k single plane [bh][s][d]
__device__ __half g_vt0[4194304], g_vt1[4194304];   // vT 2-plane [bh][d][s]
__device__ __half g_c0[4194304],  g_c1[4194304];    // ctx 2-plane [m][e]

// ---------------------------------------------------------------------------
// PTX helpers
// ---------------------------------------------------------------------------
__device__ __forceinline__ uint32_t smem_u32(const void* p) {
    uint32_t a;
    asm("{ .reg .u64 t; cvta.to.shared.u64 t, %1; cvt.u32.u64 %0, t; }" : "=r"(a) : "l"(p));
    return a;
}

__device__ __forceinline__ void ldsm4(uint32_t r[4], uint32_t addr) {
    asm volatile("ldmatrix.sync.aligned.m8n8.x4.shared.b16 {%0,%1,%2,%3}, [%4];"
        : "=r"(r[0]), "=r"(r[1]), "=r"(r[2]), "=r"(r[3]) : "r"(addr));
}

__device__ __forceinline__ void mma_f16(float* c, const uint32_t* a, const uint32_t* b) {
    asm volatile(
        "mma.sync.aligned.m16n8k16.row.col.f32.f16.f16.f32 "
        "{%0,%1,%2,%3}, {%4,%5,%6,%7}, {%8,%9}, {%0,%1,%2,%3};\n"
        : "+f"(c[0]), "+f"(c[1]), "+f"(c[2]), "+f"(c[3])
        : "r"(a[0]), "r"(a[1]), "r"(a[2]), "r"(a[3]), "r"(b[0]), "r"(b[1]));
}

#define CP16(dst, src) \
    asm volatile("cp.async.cg.shared.global [%0], [%1], 16;" :: "r"(dst), "l"(src))
#define CP_COMMIT() asm volatile("cp.async.commit_group;")
#define CP_WAIT(N)  asm volatile("cp.async.wait_group %0;" :: "n"(N))

__device__ __forceinline__ uint32_t pack_h2(float x, float y) {
    __half2 h = __floats2half2_rn(x, y);
    return *(uint32_t*)&h;
}

// ---------------------------------------------------------------------------
// Merged split kernel: fp32 -> fp16 hi/lo planes (Wo: hi only).
// ---------------------------------------------------------------------------
__global__ __launch_bounds__(256) void split_all_kernel(
    const float* __restrict__ x,  const float* __restrict__ Wq,
    const float* __restrict__ Wk, const float* __restrict__ Wv,
    const float* __restrict__ Wo)
{
    const int NX = 1048576;
    const int NW = 262144;
    const int NT = NX + 4 * NW;
    for (int i4 = blockIdx.x * 256 + threadIdx.x; i4 < NT; i4 += gridDim.x * 256) {
        const float* src; __half *d0, *d1; int idx; bool lo = true;
        if (i4 < NX) { src = x; d0 = g_xs0; d1 = g_xs1; idx = i4; }
        else {
            int r = i4 - NX; int w = r / NW; idx = r - w * NW;
            if (w == 0)      { src = Wq; d0 = g_wb0;           d1 = g_wb1; }
            else if (w == 1) { src = Wk; d0 = g_wb0 + 1048576; d1 = g_wb1 + 1048576; }
            else if (w == 2) { src = Wv; d0 = g_wb0 + 2097152; d1 = g_wb1 + 2097152; }
            else             { src = Wo; d0 = g_wo0;           d1 = 0; lo = false; }
        }
        float4 a = ((const float4*)src)[idx];
        __half h0 = __float2half_rn(a.x), h1 = __float2half_rn(a.y);
        __half h2 = __float2half_rn(a.z), h3 = __float2half_rn(a.w);
        uint2 vh;
        vh.x = pack_h2(0, 0); // placeholder, overwritten below
        {
            __half2 p01; p01.x = h0; p01.y = h1;
            __half2 p23; p23.x = h2; p23.y = h3;
            vh.x = *(uint32_t*)&p01; vh.y = *(uint32_t*)&p23;
        }
        *(uint2*)(d0 + 4 * (size_t)idx) = vh;
        if (lo) {
            uint2 vl;
            vl.x = pack_h2(a.x - __half2float(h0), a.y - __half2float(h1));
            vl.y = pack_h2(a.z - __half2float(h2), a.w - __half2float(h3));
            *(uint2*)(d1 + 4 * (size_t)idx) = vl;
        }
    }
}

// ---------------------------------------------------------------------------
// QKV projection: 128x128 tile, 512 threads, fp16x2 3-pass (exact).
// grid (32, 24). q pre-scaled by 0.125*log2(e); k stored single-plane.
// ---------------------------------------------------------------------------
#define GP_SMEM 147456

__global__ __launch_bounds__(512) void qkv_mma_kernel(
    const float* __restrict__ bq, const float* __restrict__ bk,
    const float* __restrict__ bv)
{
    extern __shared__ char smem[];
    const int tid = threadIdx.x;
    const int lane = tid & 31;
    const int wid = tid >> 5;
    const int wr = wid >> 2;
    const int wc = wid & 3;
    const int m0 = blockIdx.x * 128;
    const int n0 = blockIdx.y * 128;
    uint32_t sb = smem_u32(smem);

    float acc[2][4][4];
    #pragma unroll
    for (int mt = 0; mt < 2; mt++)
        #pragma unroll
        for (int nt = 0; nt < 4; nt++)
            #pragma unroll
            for (int j = 0; j < 4; j++) acc[mt][nt][j] = 0.f;

    const char* planes[4] = {
        (const char*)(g_xs0 + (size_t)m0 * 1024), (const char*)(g_xs1 + (size_t)m0 * 1024),
        (const char*)(g_wb0 + (size_t)n0 * 1024), (const char*)(g_wb1 + (size_t)n0 * 1024) };

    auto issue = [&](int ks) {
        uint32_t base = sb + (uint32_t)(ks & 1) * 73728;
        #pragma unroll
        for (int j = 0; j < 8; j++) {
            int id = j * 512 + tid;
            int plane = id >> 10;
            int wp = id & 1023;
            int row = wp >> 3, c = wp & 7;
            CP16(base + plane * 18432 + row * 144 + c * 16,
                 planes[plane] + (size_t)row * 2048 + (size_t)ks * 128 + c * 16);
        }
    };

    uint32_t aaddr[2];
    #pragma unroll
    for (int mt = 0; mt < 2; mt++)
        aaddr[mt] = sb + (uint32_t)((wr * 32 + mt * 16 + (lane & 15)) * 144 + (lane >> 4) * 16);

    const uint32_t bgrp = sb + 36864
        + (uint32_t)((wc * 32 + ((lane >> 4) << 3) + (lane & 7)) * 144)
        + ((lane & 8) ? 16u : 0u);

    issue(0); CP_COMMIT();

    for (int ks = 0; ks < 16; ks++) {
        CP_WAIT(0);
        __syncthreads();
        if (ks + 1 < 16) { issue(ks + 1); CP_COMMIT(); }

        const uint32_t soff = (uint32_t)(ks & 1) * 73728;
        #pragma unroll
        for (int kc = 0; kc < 4; kc++) {
            const uint32_t ko = soff + kc * 32;
            uint32_t aH[2][4], aL[2][4];
            #pragma unroll
            for (int mt = 0; mt < 2; mt++) {
                ldsm4(aH[mt], aaddr[mt] + ko);
                ldsm4(aL[mt], aaddr[mt] + ko + 18432);
            }
            uint32_t bH01[4], bH23[4], bL01[4], bL23[4];
            ldsm4(bH01, bgrp + ko);
            ldsm4(bH23, bgrp + ko + 2304);
            ldsm4(bL01, bgrp + ko + 18432);
            ldsm4(bL23, bgrp + ko + 18432 + 2304);

            #pragma unroll
            for (int mt = 0; mt < 2; mt++) {
                mma_f16(acc[mt][0], aH[mt], bH01 + 0);
                mma_f16(acc[mt][1], aH[mt], bH01 + 2);
                mma_f16(acc[mt][2], aH[mt], bH23 + 0);
                mma_f16(acc[mt][3], aH[mt], bH23 + 2);
            }
            #pragma unroll
            for (int mt = 0; mt < 2; mt++) {
                mma_f16(acc[mt][0], aH[mt], bL01 + 0);
                mma_f16(acc[mt][1], aH[mt], bL01 + 2);
                mma_f16(acc[mt][2], aH[mt], bL23 + 0);
                mma_f16(acc[mt][3], aH[mt], bL23 + 2);
            }
            #pragma unroll
            for (int mt = 0; mt < 2; mt++) {
                mma_f16(acc[mt][0], aL[mt], bH01 + 0);
                mma_f16(acc[mt][1], aL[mt], bH01 + 2);
                mma_f16(acc[mt][2], aL[mt], bH23 + 0);
                mma_f16(acc[mt][3], aL[mt], bH23 + 2);
            }
        }
    }

    const int which = n0 >> 10;
    const int fbase = n0 & 1023;
    const float* bias = (which == 0) ? bq : (which == 1) ? bk : bv;
    const float psc = (which == 0) ? 0.125f * 1.44269504088896340736f : 1.0f;

    #pragma unroll
    for (int mt = 0; mt < 2; mt++) {
        #pragma unroll
        for (int nt = 0; nt < 4; nt++) {
            int f = fbase + wc * 32 + nt * 8 + (lane & 3) * 2;
            int h = f >> 6, d = f & 63;
            float bz0 = bias[f], bz1 = bias[f + 1];
            #pragma unroll
            for (int half = 0; half < 2; half++) {
                int m = m0 + wr * 32 + mt * 16 + (lane >> 2) + half * 8;
                int b = m >> 10, t = m & 1023;
                float v0 = (acc[mt][nt][half * 2 + 0] + bz0) * psc;
                float v1 = (acc[mt][nt][half * 2 + 1] + bz1) * psc;
                __half h0 = __float2half_rn(v0);
                __half h1 = __float2half_rn(v1);
                uint32_t ph = pack_h2(v0, v1);       // rounds same as h0,h1
                if (which == 0) {
                    uint32_t pl = pack_h2(v0 - __half2float(h0), v1 - __half2float(h1));
                    size_t idx = (((size_t)(b * 16 + h)) * 1024 + t) * 64 + d;
                    *(uint32_t*)&g_q0[idx] = ph;
                    *(uint32_t*)&g_q1[idx] = pl;
                } else if (which == 1) {
                    size_t idx = (((size_t)(b * 16 + h)) * 1024 + t) * 64 + d;
                    *(uint32_t*)&g_k0[idx] = ph;     // k single plane
                } else {
                    float l0 = v0 - __half2float(h0);
                    float l1 = v1 - __half2float(h1);
                    size_t base = ((size_t)(b * 16 + h) * 64 + d) * 1024 + t;
                    g_vt0[base] = h0;        g_vt1[base] = __float2half_rn(l0);
                    g_vt0[base + 1024] = h1; g_vt1[base + 1024] = __float2half_rn(l1);
                }
            }
        }
    }
}

// ---------------------------------------------------------------------------
// Flash attention (R12 shape): 128-row Q tiles, split-K warp pairs,
// grid (8, 64), 512 threads. fp16: scores 2-pass (q-split, k single);
// P@V 2-pass (P single pack, V 2-plane). Base-2 softmax.
// ---------------------------------------------------------------------------
#define FQ0 0
#define FQ1 18432
#define FKV 36864
#define FKV_STRIDE 53248
#define FV0_OFF 18432
#define FV1_OFF 35840
#define FL_SMEM (36864 + 2*53248)

__global__ __launch_bounds__(512, 1) void flash_kernel(
    const float* __restrict__ noise, const float* __restrict__ theta)
{
    extern __shared__ char sm[];
    __half* q0s = (__half*)(sm + FQ0);
    __half* q1s = (__half*)(sm + FQ1);
    uint32_t sb = smem_u32(sm);

    const int tid = threadIdx.x;
    const int lane = tid & 31;
    const int wid = tid >> 5;
    const int pw = wid & 7;
    const int khalf = wid >> 3;
    const int m0 = blockIdx.x * 128;
    const int bh = blockIdx.y;
    const int bb = bh >> 4, hh = bh & 15;

    const char* gk0 = (const char*)(g_k0 + (size_t)bh * 65536);
    const char* gv0 = (const char*)(g_vt0 + (size_t)bh * 65536);
    const char* gv1 = (const char*)(g_vt1 + (size_t)bh * 65536);

    auto issue = [&](int s0, int b) {
        uint32_t base = sb + FKV + (uint32_t)b * FKV_STRIDE;
        #pragma unroll
        for (int j = 0; j < 2; j++) {
            int idx = j * 512 + tid;       // 0..1023
            int row = idx >> 3, c = idx & 7;
            CP16(base + row * 144 + c * 16,
                 gk0 + (size_t)(s0 + row) * 128 + c * 16);
            int vrow = idx >> 4, vc = idx & 15;
            CP16(base + FV0_OFF + vrow * 272 + vc * 16,
                 gv0 + (size_t)vrow * 2048 + (size_t)s0 * 2 + vc * 16);
            CP16(base + FV1_OFF + vrow * 272 + vc * 16,
                 gv1 + (size_t)vrow * 2048 + (size_t)s0 * 2 + vc * 16);
        }
    };

    issue(0, 0); CP_COMMIT();

    float Tm = 0.f;
    #pragma unroll
    for (int h = 0; h < 16; h++) {
        float sg = 1.f / (1.f + expf(-theta[h]));
        Tm += fabsf(sinf(2.f * sg * 1.57079632679489662f));
    }
    Tm *= (1.f / 16.f);
    const float inv_keep = 1.f / (1.f - Tm + 1e-8f);

    // Q tile (128 rows x 64 d, 2 planes)
    {
        const __half* gq0 = g_q0 + (size_t)bh * 65536 + (size_t)m0 * 64;
        const __half* gq1 = g_q1 + (size_t)bh * 65536 + (size_t)m0 * 64;
        #pragma unroll
        for (int i = 0; i < 2; i++) {
            int idx = i * 512 + tid;
            int row = idx >> 3, c = idx & 7;
            *(float4*)(q0s + row * 72 + c * 8) = *(const float4*)(gq0 + row * 64 + c * 8);
            *(float4*)(q1s + row * 72 + c * 8) = *(const float4*)(gq1 + row * 64 + c * 8);
        }
    }
    __syncthreads();

    uint32_t qH[4][4], qL[4][4];
    {
        uint32_t qa0 = smem_u32(q0s + (pw * 16 + (lane & 15)) * 72 + (lane >> 4) * 8);
        uint32_t qa1 = smem_u32(q1s + (pw * 16 + (lane & 15)) * 72 + (lane >> 4) * 8);
        #pragma unroll
        for (int kc = 0; kc < 4; kc++) {
            ldsm4(qH[kc], qa0 + kc * 32);
            ldsm4(qL[kc], qa1 + kc * 32);
        }
    }

    const uint32_t lrow8 = ((lane >> 4) << 3) + (lane & 7);
    const uint32_t khoff = (lane & 8) ? 16u : 0u;
    const uint32_t kgrp = lrow8 * 144 + khoff + (uint32_t)khalf * 9216;
    const uint32_t vgrp = lrow8 * 272 + khoff + (uint32_t)khalf * 128;

    const int rl = lane >> 2;
    const int row_q = pw * 16 + rl;
    const float* nz_base = noise + (size_t)bh * 1048576
                         + (size_t)(m0 + row_q) * 1024 + khalf * 64 + (lane & 3) * 2;

    float m_prev0 = -1e30f, m_prev1 = -1e30f;
    float l0 = 0.f, l1 = 0.f;
    float O[8][4];
    #pragma unroll
    for (int nt = 0; nt < 8; nt++)
        #pragma unroll
        for (int j = 0; j < 4; j++) O[nt][j] = 0.f;

    for (int it = 0; it < 8; it++) {
        const int s0 = it * 128;
        const int buf = it & 1;
        CP_WAIT(0);
        __syncthreads();
        if (it + 1 < 8) issue(s0 + 128, buf ^ 1);
        CP_COMMIT();

        const uint32_t kbase = sb + FKV + (uint32_t)buf * FKV_STRIDE + kgrp;
        const uint32_t vbase = sb + FKV + (uint32_t)buf * FKV_STRIDE + FV0_OFF + vgrp;

        // ---- scores (16 x 64): 2-pass qH/qL vs kH ----
        float Sa[8][4];
        #pragma unroll
        for (int nt = 0; nt < 8; nt++)
            #pragma unroll
            for (int j = 0; j < 4; j++) Sa[nt][j] = 0.f;

        #pragma unroll
        for (int kc = 0; kc < 4; kc++) {
            #pragma unroll
            for (int ntg = 0; ntg < 4; ntg += 2) {
                uint32_t tH0[4], tH1[4];
                uint32_t a0 = kbase + ntg * 2304 + kc * 32;
                ldsm4(tH0, a0);
                ldsm4(tH1, a0 + 2304);
                mma_f16(Sa[2*ntg],   qH[kc], tH0 + 0);
                mma_f16(Sa[2*ntg+1], qH[kc], tH0 + 2);
                mma_f16(Sa[2*ntg+2], qH[kc], tH1 + 0);
                mma_f16(Sa[2*ntg+3], qH[kc], tH1 + 2);
                mma_f16(Sa[2*ntg],   qL[kc], tH0 + 0);
                mma_f16(Sa[2*ntg+1], qL[kc], tH0 + 2);
                mma_f16(Sa[2*ntg+2], qL[kc], tH1 + 0);
                mma_f16(Sa[2*ntg+3], qL[kc], tH1 + 2);
            }
        }

        // ---- per-warp online softmax (base-2) ----
        float mt0 = -1e30f, mt1 = -1e30f;
        #pragma unroll
        for (int nt = 0; nt < 8; nt++) {
            mt0 = fmaxf(mt0, fmaxf(Sa[nt][0], Sa[nt][1]));
            mt1 = fmaxf(mt1, fmaxf(Sa[nt][2], Sa[nt][3]));
        }
        mt0 = fmaxf(mt0, __shfl_xor_sync(0xffffffffu, mt0, 1));
        mt0 = fmaxf(mt0, __shfl_xor_sync(0xffffffffu, mt0, 2));
        mt1 = fmaxf(mt1, __shfl_xor_sync(0xffffffffu, mt1, 1));
        mt1 = fmaxf(mt1, __shfl_xor_sync(0xffffffffu, mt1, 2));

        float mn0 = fmaxf(m_prev0, mt0), mn1 = fmaxf(m_prev1, mt1);
        float f0 = exp2f(m_prev0 - mn0), f1 = exp2f(m_prev1 - mn1);
        m_prev0 = mn0; m_prev1 = mn1;
        l0 *= f0; l1 *= f1;
        #pragma unroll
        for (int nt = 0; nt < 8; nt++) {
            O[nt][0] *= f0; O[nt][1] *= f0;
            O[nt][2] *= f1; O[nt][3] *= f1;
        }

        float rs0 = 0.f, rs1 = 0.f;
        #pragma unroll
        for (int nt = 0; nt < 8; nt++) {
            Sa[nt][0] = exp2f(Sa[nt][0] - mn0);
            Sa[nt][1] = exp2f(Sa[nt][1] - mn0);
            Sa[nt][2] = exp2f(Sa[nt][2] - mn1);
            Sa[nt][3] = exp2f(Sa[nt][3] - mn1);
            rs0 += Sa[nt][0] + Sa[nt][1];
            rs1 += Sa[nt][2] + Sa[nt][3];
        }
        rs0 += __shfl_xor_sync(0xffffffffu, rs0, 1);
        rs0 += __shfl_xor_sync(0xffffffffu, rs0, 2);
        rs1 += __shfl_xor_sync(0xffffffffu, rs1, 1);
        rs1 += __shfl_xor_sync(0xffffffffu, rs1, 2);
        l0 += rs0; l1 += rs1;

        // ---- dropout ----
        const float* nz0 = nz_base + s0;
        #pragma unroll
        for (int nt = 0; nt < 8; nt++) {
            float2 a = *(const float2*)(nz0 + nt * 8);
            float2 b = *(const float2*)(nz0 + 8192 + nt * 8);
            Sa[nt][0] *= (a.x > Tm) ? inv_keep : 0.f;
            Sa[nt][1] *= (a.y > Tm) ? inv_keep : 0.f;
            Sa[nt][2] *= (b.x > Tm) ? inv_keep : 0.f;
            Sa[nt][3] *= (b.y > Tm) ? inv_keep : 0.f;
        }

        // ---- P @ V: P single pack, V 2-plane, 2-pass ----
        #pragma unroll
        for (int kc = 0; kc < 4; kc++) {
            uint32_t aP[4];
            aP[0] = pack_h2(Sa[2*kc][0],   Sa[2*kc][1]);
            aP[1] = pack_h2(Sa[2*kc][2],   Sa[2*kc][3]);
            aP[2] = pack_h2(Sa[2*kc+1][0], Sa[2*kc+1][1]);
            aP[3] = pack_h2(Sa[2*kc+1][2], Sa[2*kc+1][3]);
            #pragma unroll
            for (int ntg = 0; ntg < 4; ntg += 2) {
                uint32_t vH0[4], vL0[4], vH1[4], vL1[4];
                uint32_t a0 = vbase + ntg * 4352 + kc * 32;
                ldsm4(vH0, a0);
                ldsm4(vL0, a0 + 17408);
                ldsm4(vH1, a0 + 4352);
                ldsm4(vL1, a0 + 4352 + 17408);
                mma_f16(O[2*ntg],   aP, vH0 + 0);
                mma_f16(O[2*ntg+1], aP, vH0 + 2);
                mma_f16(O[2*ntg+2], aP, vH1 + 0);
                mma_f16(O[2*ntg+3], aP, vH1 + 2);
                mma_f16(O[2*ntg],   aP, vL0 + 0);
                mma_f16(O[2*ntg+1], aP, vL0 + 2);
                mma_f16(O[2*ntg+2], aP, vL1 + 0);
                mma_f16(O[2*ntg+3], aP, vL1 + 2);
            }
        }
    }

    // ---- merge split-K halves (scratch in dead KV buffer 0) ----
    __syncthreads();
    float* sml = (float*)(sm + FKV);            // [16 warps][16 rows][2] = 2 KB
    float* Osm = (float*)(sm + FKV + 2048);     // [8 pairs][16 rows][64] fp32 = 32 KB

    if ((lane & 3) == 0) {
        sml[(wid * 16 + rl) * 2 + 0]     = m_prev0;
        sml[(wid * 16 + rl) * 2 + 1]     = l0;
        sml[(wid * 16 + rl + 8) * 2 + 0] = m_prev1;
        sml[(wid * 16 + rl + 8) * 2 + 1] = l1;
    }
    __syncthreads();

    const int pwid = wid ^ 8;
    float pm0 = sml[(pwid * 16 + rl) * 2 + 0],     pl0 = sml[(pwid * 16 + rl) * 2 + 1];
    float pm1 = sml[(pwid * 16 + rl + 8) * 2 + 0], pl1 = sml[(pwid * 16 + rl + 8) * 2 + 1];
    float M0 = fmaxf(m_prev0, pm0), M1 = fmaxf(m_prev1, pm1);
    float e0 = exp2f(m_prev0 - M0), e1 = exp2f(m_prev1 - M1);
    float pe0 = exp2f(pm0 - M0),    pe1 = exp2f(pm1 - M1);
    float L0 = l0 * e0 + pl0 * pe0;
    float L1 = l1 * e1 + pl1 * pe1;

    float* Opair = Osm + pw * 1024;
    if (khalf == 1) {
        #pragma unroll
        for (int nt = 0; nt < 8; nt++) {
            int d = nt * 8 + (lane & 3) * 2;
            float2 v0; v0.x = O[nt][0] * e0; v0.y = O[nt][1] * e0;
            float2 v1; v1.x = O[nt][2] * e1; v1.y = O[nt][3] * e1;
            *(float2*)(Opair + rl * 64 + d)       = v0;
            *(float2*)(Opair + (rl + 8) * 64 + d) = v1;
        }
    }
    __syncthreads();

    if (khalf == 0) {
        const float iL0 = 1.f / L0, iL1 = 1.f / L1;
        const int t0 = m0 + row_q;
        #pragma unroll
        for (int nt = 0; nt < 8; nt++) {
            int d = nt * 8 + (lane & 3) * 2;
            float2 ob0 = *(float2*)(Opair + rl * 64 + d);
            float2 ob1 = *(float2*)(Opair + (rl + 8) * 64 + d);
            float v0 = (O[nt][0] * e0 + ob0.x) * iL0;
            float v1 = (O[nt][1] * e0 + ob0.y) * iL0;
            float v2 = (O[nt][2] * e1 + ob1.x) * iL1;
            float v3 = (O[nt][3] * e1 + ob1.y) * iL1;

            __half h0 = __float2half_rn(v0), h1 = __float2half_rn(v1);
            size_t idx = ((size_t)bb * 1024 + t0) * 1024 + hh * 64 + d;
            *(uint32_t*)&g_c0[idx] = pack_h2(v0, v1);
            *(uint32_t*)&g_c1[idx] = pack_h2(v0 - __half2float(h0), v1 - __half2float(h1));

            __half h2 = __float2half_rn(v2), h3 = __float2half_rn(v3);
            size_t idx2 = ((size_t)bb * 1024 + t0 + 8) * 1024 + hh * 64 + d;
            *(uint32_t*)&g_c0[idx2] = pack_h2(v2, v3);
            *(uint32_t*)&g_c1[idx2] = pack_h2(v2 - __half2float(h2), v3 - __half2float(h3));
        }
    }
}

// ---------------------------------------------------------------------------
// Output projection: 128x128 tile, 512 threads, fp16 2-pass
// (ctx 2-plane, Wo single). grid (32, 8).
// Smem/stage 55296: A0@0, A1@18432, B@36864.
// ---------------------------------------------------------------------------
#define OP_SMEM (2*55296)

__global__ __launch_bounds__(512) void outproj_mma_kernel(
    const float* __restrict__ bo, float* __restrict__ out)
{
    extern __shared__ char smem[];
    const int tid = threadIdx.x;
    const int lane = tid & 31;
    const int wid = tid >> 5;
    const int wr = wid >> 2;
    const int wc = wid & 3;
    const int m0 = blockIdx.x * 128;
    const int n0 = blockIdx.y * 128;
    uint32_t sb = smem_u32(smem);

    float acc[2][4][4];
    #pragma unroll
    for (int mt = 0; mt < 2; mt++)
        #pragma unroll
        for (int nt = 0; nt < 4; nt++)
            #pragma unroll
            for (int j = 0; j < 4; j++) acc[mt][nt][j] = 0.f;

    const char* planes[3] = {
        (const char*)(g_c0 + (size_t)m0 * 1024), (const char*)(g_c1 + (size_t)m0 * 1024),
        (const char*)(g_wo0 + (size_t)n0 * 1024) };

    // 3 planes x 128 rows x 8 chunks = 3072 chunks, 6 per thread
    auto issue = [&](int ks) {
        uint32_t base = sb + (uint32_t)(ks & 1) * 55296;
        #pragma unroll
        for (int j = 0; j < 6; j++) {
            int id = j * 512 + tid;
            int plane = id >> 10;
            int wp = id & 1023;
            int row = wp >> 3, c = wp & 7;
            CP16(base + plane * 18432 + row * 144 + c * 16,
                 planes[plane] + (size_t)row * 2048 + (size_t)ks * 128 + c * 16);
        }
    };

    uint32_t aaddr[2];
    #pragma unroll
    for (int mt = 0; mt < 2; mt++)
        aaddr[mt] = sb + (uint32_t)((wr * 32 + mt * 16 + (lane & 15)) * 144 + (lane >> 4) * 16);

    const uint32_t bgrp = sb + 36864
        + (uint32_t)((wc * 32 + ((lane >> 4) << 3) + (lane & 7)) * 144)
        + ((lane & 8) ? 16u : 0u);

    issue(0); CP_COMMIT();

    for (int ks = 0; ks < 16; ks++) {
        CP_WAIT(0);
        __syncthreads();
        if (ks + 1 < 16) { issue(ks + 1); CP_COMMIT(); }

        const uint32_t soff = (uint32_t)(ks & 1) * 55296;
        #pragma unroll
        for (int kc = 0; kc < 4; kc++) {
            const uint32_t ko = soff + kc * 32;
            uint32_t aH[2][4], aL[2][4];
            #pragma unroll
            for (int mt = 0; mt < 2; mt++) {
                ldsm4(aH[mt], aaddr[mt] + ko);
                ldsm4(aL[mt], aaddr[mt] + ko + 18432);
            }
            uint32_t bH01[4], bH23[4];
            ldsm4(bH01, bgrp + ko);
            ldsm4(bH23, bgrp + ko + 2304);

            #pragma unroll
            for (int mt = 0; mt < 2; mt++) {
                mma_f16(acc[mt][0], aH[mt], bH01 + 0);
                mma_f16(acc[mt][1], aH[mt], bH01 + 2);
                mma_f16(acc[mt][2], aH[mt], bH23 + 0);
                mma_f16(acc[mt][3], aH[mt], bH23 + 2);
            }
            #pragma unroll
            for (int mt = 0; mt < 2; mt++) {
                mma_f16(acc[mt][0], aL[mt], bH01 + 0);
                mma_f16(acc[mt][1], aL[mt], bH01 + 2);
                mma_f16(acc[mt][2], aL[mt], bH23 + 0);
                mma_f16(acc[mt][3], aL[mt], bH23 + 2);
            }
        }
    }

    #pragma unroll
    for (int mt = 0; mt < 2; mt++)
        #pragma unroll
        for (int nt = 0; nt < 4; nt++) {
            int f = n0 + wc * 32 + nt * 8 + (lane & 3) * 2;
            float bz0 = bo[f], bz1 = bo[f + 1];
            #pragma unroll
            for (int half = 0; half < 2; half++) {
                int m = m0 + wr * 32 + mt * 16 + (lane >> 2) + half * 8;
                float2 v;
                v.x = acc[mt][nt][half * 2 + 0] + bz0;
                v.y = acc[mt][nt][half * 2 + 1] + bz1;
                *(float2*)&out[(size_t)m * 1024 + f] = v;
            }
        }
}

// ---------------------------------------------------------------------------
extern "C" void kernel_launch(void* const* d_in, const int* in_sizes, int n_in,
                              void* d_out, int out_size)
{
    (void)in_sizes; (void)n_in; (void)out_size;
    const float* x     = (const float*)d_in[0];
    const float* noise = (const float*)d_in[1];
    const float* Wq    = (const float*)d_in[2];
    const float* bq    = (const float*)d_in[3];
    const float* Wk    = (const float*)d_in[4];
    const float* bk    = (const float*)d_in[5];
    const float* Wv    = (const float*)d_in[6];
    const float* bv    = (const float*)d_in[7];
    const float* Wo    = (const float*)d_in[8];
    const float* bo    = (const float*)d_in[9];
    const float* theta = (const float*)d_in[10];
    // d_in[11] = corr_w: unused (per-head bias cancels in softmax)
    float* out = (float*)d_out;

    cudaFuncSetAttribute(flash_kernel,
        cudaFuncAttributeMaxDynamicSharedMemorySize, FL_SMEM);
    cudaFuncSetAttribute(qkv_mma_kernel,
        cudaFuncAttributeMaxDynamicSharedMemorySize, GP_SMEM);
    cudaFuncSetAttribute(outproj_mma_kernel,
        cudaFuncAttributeMaxDynamicSharedMemorySize, OP_SMEM);

    split_all_kernel<<<4096, 256>>>(x, Wq, Wk, Wv, Wo);
    qkv_mma_kernel<<<dim3(32, 24), 512, GP_SMEM>>>(bq, bk, bv);
    flash_kernel<<<dim3(8, 64), 512, FL_SMEM>>>(noise, theta);
    outproj_mma_kernel<<<dim3(32, 8), 512, OP_SMEM>>>(bo, out);
}

// round 16
// speedup vs baseline: 1.6110x; 1.3022x over previous
#include <cuda_runtime.h>
#include <cuda_fp16.h>
#include <cstdint>
#include <math.h>

// Problem: B=4, H=16, T=1024, D=64, E=1024, M=B*T=4096, BH=64
// fp16 split GEMMs. qkv: 2-pass (x 2-plane, W single). scores: 2-pass
// (q 2-plane, k single). P@V: 1-pass. outproj: 2-pass (ctx 2-plane, Wo single).

// ---------------------------------------------------------------------------
// Device-global scratch (fp16)
// ---------------------------------------------------------------------------
__device__ __half g_xs0[4194304], g_xs1[4194304];   // x split   [4096][1024]
__device__ __half g_wb0[3145728];                   // Wq|Wk|Wv single plane
__device__ __half g_wo0[1048576];                   // Wo single plane
__device__ __half g_q0[4194304],  g_q1[4194304];    // q (scaled 0.125*log2e) 2-plane
__device__ __half g_k0[4194304];                    // k single plane [bh][s][d]
__device__ __half g_vt0[4194304];                   // vT single plane [bh][d][s]
__device__ __half g_c0[4194304],  g_c1[4194304];    // ctx 2-plane [m][e]

// ---------------------------------------------------------------------------
// PTX helpers
// ---------------------------------------------------------------------------
__device__ __forceinline__ uint32_t smem_u32(const void* p) {
    uint32_t a;
    asm("{ .reg .u64 t; cvta.to.shared.u64 t, %1; cvt.u32.u64 %0, t; }" : "=r"(a) : "l"(p));
    return a;
}

__device__ __forceinline__ void ldsm4(uint32_t r[4], uint32_t addr) {
    asm volatile("ldmatrix.sync.aligned.m8n8.x4.shared.b16 {%0,%1,%2,%3}, [%4];"
        : "=r"(r[0]), "=r"(r[1]), "=r"(r[2]), "=r"(r[3]) : "r"(addr));
}

__device__ __forceinline__ void mma_f16(float* c, const uint32_t* a, const uint32_t* b) {
    asm volatile(
        "mma.sync.aligned.m16n8k16.row.col.f32.f16.f16.f32 "
        "{%0,%1,%2,%3}, {%4,%5,%6,%7}, {%8,%9}, {%0,%1,%2,%3};\n"
        : "+f"(c[0]), "+f"(c[1]), "+f"(c[2]), "+f"(c[3])
        : "r"(a[0]), "r"(a[1]), "r"(a[2]), "r"(a[3]), "r"(b[0]), "r"(b[1]));
}

#define CP16(dst, src) \
    asm volatile("cp.async.cg.shared.global [%0], [%1], 16;" :: "r"(dst), "l"(src))
#define CP_COMMIT() asm volatile("cp.async.commit_group;")
#define CP_WAIT(N)  asm volatile("cp.async.wait_group %0;" :: "n"(N))

__device__ __forceinline__ uint32_t pack_h2(float x, float y) {
    __half2 h = __floats2half2_rn(x, y);
    return *(uint32_t*)&h;
}

// ---------------------------------------------------------------------------
// Merged split kernel: x -> 2 fp16 planes; Wq/Wk/Wv/Wo -> 1 plane each.
// ---------------------------------------------------------------------------
__global__ __launch_bounds__(256) void split_all_kernel(
    const float* __restrict__ x,  const float* __restrict__ Wq,
    const float* __restrict__ Wk, const float* __restrict__ Wv,
    const float* __restrict__ Wo)
{
    const int NX = 1048576;
    const int NW = 262144;
    const int NT = NX + 4 * NW;
    for (int i4 = blockIdx.x * 256 + threadIdx.x; i4 < NT; i4 += gridDim.x * 256) {
        const float* src; __half *d0; int idx; bool lo = false;
        if (i4 < NX) { src = x; d0 = g_xs0; idx = i4; lo = true; }
        else {
            int r = i4 - NX; int w = r / NW; idx = r - w * NW;
            if (w == 0)      { src = Wq; d0 = g_wb0; }
            else if (w == 1) { src = Wk; d0 = g_wb0 + 1048576; }
            else if (w == 2) { src = Wv; d0 = g_wb0 + 2097152; }
            else             { src = Wo; d0 = g_wo0; }
        }
        float4 a = ((const float4*)src)[idx];
        __half h0 = __float2half_rn(a.x), h1 = __float2half_rn(a.y);
        __half h2 = __float2half_rn(a.z), h3 = __float2half_rn(a.w);
        uint2 vh;
        { __half2 p01; p01.x = h0; p01.y = h1;
          __half2 p23; p23.x = h2; p23.y = h3;
          vh.x = *(uint32_t*)&p01; vh.y = *(uint32_t*)&p23; }
        *(uint2*)(d0 + 4 * (size_t)idx) = vh;
        if (lo) {
            uint2 vl;
            vl.x = pack_h2(a.x - __half2float(h0), a.y - __half2float(h1));
            vl.y = pack_h2(a.z - __half2float(h2), a.w - __half2float(h3));
            *(uint2*)(g_xs1 + 4 * (size_t)idx) = vl;
        }
    }
}

// ---------------------------------------------------------------------------
// QKV projection: 128x128 tile, 512 threads, fp16 2-pass (xH/xL vs W).
// grid (32, 24). Smem/stage 55296: A0@0 A1@18432 B@36864.
// q pre-scaled by 0.125*log2(e); k and vT stored single-plane.
// ---------------------------------------------------------------------------
#define GP_SMEM (2*55296)

__global__ __launch_bounds__(512) void qkv_mma_kernel(
    const float* __restrict__ bq, const float* __restrict__ bk,
    const float* __restrict__ bv)
{
    extern __shared__ char smem[];
    const int tid = threadIdx.x;
    const int lane = tid & 31;
    const int wid = tid >> 5;
    const int wr = wid >> 2;
    const int wc = wid & 3;
    const int m0 = blockIdx.x * 128;
    const int n0 = blockIdx.y * 128;
    uint32_t sb = smem_u32(smem);

    float acc[2][4][4];
    #pragma unroll
    for (int mt = 0; mt < 2; mt++)
        #pragma unroll
        for (int nt = 0; nt < 4; nt++)
            #pragma unroll
            for (int j = 0; j < 4; j++) acc[mt][nt][j] = 0.f;

    const char* planes[3] = {
        (const char*)(g_xs0 + (size_t)m0 * 1024), (const char*)(g_xs1 + (size_t)m0 * 1024),
        (const char*)(g_wb0 + (size_t)n0 * 1024) };

    auto issue = [&](int ks) {
        uint32_t base = sb + (uint32_t)(ks & 1) * 55296;
        #pragma unroll
        for (int j = 0; j < 6; j++) {
            int id = j * 512 + tid;
            int plane = id >> 10;
            int wp = id & 1023;
            int row = wp >> 3, c = wp & 7;
            CP16(base + plane * 18432 + row * 144 + c * 16,
                 planes[plane] + (size_t)row * 2048 + (size_t)ks * 128 + c * 16);
        }
    };

    uint32_t aaddr[2];
    #pragma unroll
    for (int mt = 0; mt < 2; mt++)
        aaddr[mt] = sb + (uint32_t)((wr * 32 + mt * 16 + (lane & 15)) * 144 + (lane >> 4) * 16);

    const uint32_t bgrp = sb + 36864
        + (uint32_t)((wc * 32 + ((lane >> 4) << 3) + (lane & 7)) * 144)
        + ((lane & 8) ? 16u : 0u);

    issue(0); CP_COMMIT();

    for (int ks = 0; ks < 16; ks++) {
        CP_WAIT(0);
        __syncthreads();
        if (ks + 1 < 16) { issue(ks + 1); CP_COMMIT(); }

        const uint32_t soff = (uint32_t)(ks & 1) * 55296;
        #pragma unroll
        for (int kc = 0; kc < 4; kc++) {
            const uint32_t ko = soff + kc * 32;
            uint32_t aH[2][4], aL[2][4];
            #pragma unroll
            for (int mt = 0; mt < 2; mt++) {
                ldsm4(aH[mt], aaddr[mt] + ko);
                ldsm4(aL[mt], aaddr[mt] + ko + 18432);
            }
            uint32_t bH01[4], bH23[4];
            ldsm4(bH01, bgrp + ko);
            ldsm4(bH23, bgrp + ko + 2304);

            #pragma unroll
            for (int mt = 0; mt < 2; mt++) {
                mma_f16(acc[mt][0], aH[mt], bH01 + 0);
                mma_f16(acc[mt][1], aH[mt], bH01 + 2);
                mma_f16(acc[mt][2], aH[mt], bH23 + 0);
                mma_f16(acc[mt][3], aH[mt], bH23 + 2);
            }
            #pragma unroll
            for (int mt = 0; mt < 2; mt++) {
                mma_f16(acc[mt][0], aL[mt], bH01 + 0);
                mma_f16(acc[mt][1], aL[mt], bH01 + 2);
                mma_f16(acc[mt][2], aL[mt], bH23 + 0);
                mma_f16(acc[mt][3], aL[mt], bH23 + 2);
            }
        }
    }

    const int which = n0 >> 10;
    const int fbase = n0 & 1023;
    const float* bias = (which == 0) ? bq : (which == 1) ? bk : bv;
    const float psc = (which == 0) ? 0.125f * 1.44269504088896340736f : 1.0f;

    #pragma unroll
    for (int mt = 0; mt < 2; mt++) {
        #pragma unroll
        for (int nt = 0; nt < 4; nt++) {
            int f = fbase + wc * 32 + nt * 8 + (lane & 3) * 2;
            int h = f >> 6, d = f & 63;
            float bz0 = bias[f], bz1 = bias[f + 1];
            #pragma unroll
            for (int half = 0; half < 2; half++) {
                int m = m0 + wr * 32 + mt * 16 + (lane >> 2) + half * 8;
                int b = m >> 10, t = m & 1023;
                float v0 = (acc[mt][nt][half * 2 + 0] + bz0) * psc;
                float v1 = (acc[mt][nt][half * 2 + 1] + bz1) * psc;
                __half h0 = __float2half_rn(v0);
                __half h1 = __float2half_rn(v1);
                uint32_t ph = pack_h2(v0, v1);
                if (which == 0) {
                    uint32_t pl = pack_h2(v0 - __half2float(h0), v1 - __half2float(h1));
                    size_t idx = (((size_t)(b * 16 + h)) * 1024 + t) * 64 + d;
                    *(uint32_t*)&g_q0[idx] = ph;
                    *(uint32_t*)&g_q1[idx] = pl;
                } else if (which == 1) {
                    size_t idx = (((size_t)(b * 16 + h)) * 1024 + t) * 64 + d;
                    *(uint32_t*)&g_k0[idx] = ph;
                } else {
                    size_t base = ((size_t)(b * 16 + h) * 64 + d) * 1024 + t;
                    g_vt0[base] = h0;
                    g_vt0[base + 1024] = h1;
                }
            }
        }
    }
}

// ---------------------------------------------------------------------------
// Flash attention: 128-row Q tiles, split-K warp pairs, grid (8, 64),
// 512 threads. Scores 2-pass (qH/qL vs kH); P@V 1-pass (P single, V single).
// Base-2 softmax. Smem: Q 2 planes (36864) + 2 x [K 18432 | V 17408].
// ---------------------------------------------------------------------------
#define FQ0 0
#define FQ1 18432
#define FKV 36864
#define FKV_STRIDE 35840
#define FV0_OFF 18432
#define FL_SMEM (36864 + 2*35840)

__global__ __launch_bounds__(512, 1) void flash_kernel(
    const float* __restrict__ noise, const float* __restrict__ theta)
{
    extern __shared__ char sm[];
    __half* q0s = (__half*)(sm + FQ0);
    __half* q1s = (__half*)(sm + FQ1);
    uint32_t sb = smem_u32(sm);

    const int tid = threadIdx.x;
    const int lane = tid & 31;
    const int wid = tid >> 5;
    const int pw = wid & 7;
    const int khalf = wid >> 3;
    const int m0 = blockIdx.x * 128;
    const int bh = blockIdx.y;
    const int bb = bh >> 4, hh = bh & 15;

    const char* gk0 = (const char*)(g_k0 + (size_t)bh * 65536);
    const char* gv0 = (const char*)(g_vt0 + (size_t)bh * 65536);

    auto issue = [&](int s0, int b) {
        uint32_t base = sb + FKV + (uint32_t)b * FKV_STRIDE;
        #pragma unroll
        for (int j = 0; j < 2; j++) {
            int idx = j * 512 + tid;       // 0..1023
            int row = idx >> 3, c = idx & 7;
            CP16(base + row * 144 + c * 16,
                 gk0 + (size_t)(s0 + row) * 128 + c * 16);
            int vrow = idx >> 4, vc = idx & 15;
            CP16(base + FV0_OFF + vrow * 272 + vc * 16,
                 gv0 + (size_t)vrow * 2048 + (size_t)s0 * 2 + vc * 16);
        }
    };

    issue(0, 0); CP_COMMIT();

    float Tm = 0.f;
    #pragma unroll
    for (int h = 0; h < 16; h++) {
        float sg = 1.f / (1.f + expf(-theta[h]));
        Tm += fabsf(sinf(2.f * sg * 1.57079632679489662f));
    }
    Tm *= (1.f / 16.f);
    const float inv_keep = 1.f / (1.f - Tm + 1e-8f);

    // Q tile (128 rows x 64 d, 2 planes)
    {
        const __half* gq0 = g_q0 + (size_t)bh * 65536 + (size_t)m0 * 64;
        const __half* gq1 = g_q1 + (size_t)bh * 65536 + (size_t)m0 * 64;
        #pragma unroll
        for (int i = 0; i < 2; i++) {
            int idx = i * 512 + tid;
            int row = idx >> 3, c = idx & 7;
            *(float4*)(q0s + row * 72 + c * 8) = *(const float4*)(gq0 + row * 64 + c * 8);
            *(float4*)(q1s + row * 72 + c * 8) = *(const float4*)(gq1 + row * 64 + c * 8);
        }
    }
    __syncthreads();

    uint32_t qH[4][4], qL[4][4];
    {
        uint32_t qa0 = smem_u32(q0s + (pw * 16 + (lane & 15)) * 72 + (lane >> 4) * 8);
        uint32_t qa1 = smem_u32(q1s + (pw * 16 + (lane & 15)) * 72 + (lane >> 4) * 8);
        #pragma unroll
        for (int kc = 0; kc < 4; kc++) {
            ldsm4(qH[kc], qa0 + kc * 32);
            ldsm4(qL[kc], qa1 + kc * 32);
        }
    }

    const uint32_t lrow8 = ((lane >> 4) << 3) + (lane & 7);
    const uint32_t khoff = (lane & 8) ? 16u : 0u;
    const uint32_t kgrp = lrow8 * 144 + khoff + (uint32_t)khalf * 9216;
    const uint32_t vgrp = lrow8 * 272 + khoff + (uint32_t)khalf * 128;

    const int rl = lane >> 2;
    const int row_q = pw * 16 + rl;
    const float* nz_base = noise + (size_t)bh * 1048576
                         + (size_t)(m0 + row_q) * 1024 + khalf * 64 + (lane & 3) * 2;

    float m_prev0 = -1e30f, m_prev1 = -1e30f;
    float l0 = 0.f, l1 = 0.f;
    float O[8][4];
    #pragma unroll
    for (int nt = 0; nt < 8; nt++)
        #pragma unroll
        for (int j = 0; j < 4; j++) O[nt][j] = 0.f;

    for (int it = 0; it < 8; it++) {
        const int s0 = it * 128;
        const int buf = it & 1;
        CP_WAIT(0);
        __syncthreads();
        if (it + 1 < 8) issue(s0 + 128, buf ^ 1);
        CP_COMMIT();

        const uint32_t kbase = sb + FKV + (uint32_t)buf * FKV_STRIDE + kgrp;
        const uint32_t vbase = sb + FKV + (uint32_t)buf * FKV_STRIDE + FV0_OFF + vgrp;

        // ---- scores (16 x 64): 2-pass qH/qL vs kH ----
        float Sa[8][4];
        #pragma unroll
        for (int nt = 0; nt < 8; nt++)
            #pragma unroll
            for (int j = 0; j < 4; j++) Sa[nt][j] = 0.f;

        #pragma unroll
        for (int kc = 0; kc < 4; kc++) {
            #pragma unroll
            for (int ntg = 0; ntg < 4; ntg += 2) {
                uint32_t tH0[4], tH1[4];
                uint32_t a0 = kbase + ntg * 2304 + kc * 32;
                ldsm4(tH0, a0);
                ldsm4(tH1, a0 + 2304);
                mma_f16(Sa[2*ntg],   qH[kc], tH0 + 0);
                mma_f16(Sa[2*ntg+1], qH[kc], tH0 + 2);
                mma_f16(Sa[2*ntg+2], qH[kc], tH1 + 0);
                mma_f16(Sa[2*ntg+3], qH[kc], tH1 + 2);
                mma_f16(Sa[2*ntg],   qL[kc], tH0 + 0);
                mma_f16(Sa[2*ntg+1], qL[kc], tH0 + 2);
                mma_f16(Sa[2*ntg+2], qL[kc], tH1 + 0);
                mma_f16(Sa[2*ntg+3], qL[kc], tH1 + 2);
            }
        }

        // ---- per-warp online softmax (base-2) ----
        float mt0 = -1e30f, mt1 = -1e30f;
        #pragma unroll
        for (int nt = 0; nt < 8; nt++) {
            mt0 = fmaxf(mt0, fmaxf(Sa[nt][0], Sa[nt][1]));
            mt1 = fmaxf(mt1, fmaxf(Sa[nt][2], Sa[nt][3]));
        }
        mt0 = fmaxf(mt0, __shfl_xor_sync(0xffffffffu, mt0, 1));
        mt0 = fmaxf(mt0, __shfl_xor_sync(0xffffffffu, mt0, 2));
        mt1 = fmaxf(mt1, __shfl_xor_sync(0xffffffffu, mt1, 1));
        mt1 = fmaxf(mt1, __shfl_xor_sync(0xffffffffu, mt1, 2));

        float mn0 = fmaxf(m_prev0, mt0), mn1 = fmaxf(m_prev1, mt1);
        float f0 = exp2f(m_prev0 - mn0), f1 = exp2f(m_prev1 - mn1);
        m_prev0 = mn0; m_prev1 = mn1;
        l0 *= f0; l1 *= f1;
        #pragma unroll
        for (int nt = 0; nt < 8; nt++) {
            O[nt][0] *= f0; O[nt][1] *= f0;
            O[nt][2] *= f1; O[nt][3] *= f1;
        }

        float rs0 = 0.f, rs1 = 0.f;
        #pragma unroll
        for (int nt = 0; nt < 8; nt++) {
            Sa[nt][0] = exp2f(Sa[nt][0] - mn0);
            Sa[nt][1] = exp2f(Sa[nt][1] - mn0);
            Sa[nt][2] = exp2f(Sa[nt][2] - mn1);
            Sa[nt][3] = exp2f(Sa[nt][3] - mn1);
            rs0 += Sa[nt][0] + Sa[nt][1];
            rs1 += Sa[nt][2] + Sa[nt][3];
        }
        rs0 += __shfl_xor_sync(0xffffffffu, rs0, 1);
        rs0 += __shfl_xor_sync(0xffffffffu, rs0, 2);
        rs1 += __shfl_xor_sync(0xffffffffu, rs1, 1);
        rs1 += __shfl_xor_sync(0xffffffffu, rs1, 2);
        l0 += rs0; l1 += rs1;

        // ---- dropout ----
        const float* nz0 = nz_base + s0;
        #pragma unroll
        for (int nt = 0; nt < 8; nt++) {
            float2 a = *(const float2*)(nz0 + nt * 8);
            float2 b = *(const float2*)(nz0 + 8192 + nt * 8);
            Sa[nt][0] *= (a.x > Tm) ? inv_keep : 0.f;
            Sa[nt][1] *= (a.y > Tm) ? inv_keep : 0.f;
            Sa[nt][2] *= (b.x > Tm) ? inv_keep : 0.f;
            Sa[nt][3] *= (b.y > Tm) ? inv_keep : 0.f;
        }

        // ---- P @ V: 1-pass (P single pack, V single plane) ----
        #pragma unroll
        for (int kc = 0; kc < 4; kc++) {
            uint32_t aP[4];
            aP[0] = pack_h2(Sa[2*kc][0],   Sa[2*kc][1]);
            aP[1] = pack_h2(Sa[2*kc][2],   Sa[2*kc][3]);
            aP[2] = pack_h2(Sa[2*kc+1][0], Sa[2*kc+1][1]);
            aP[3] = pack_h2(Sa[2*kc+1][2], Sa[2*kc+1][3]);
            #pragma unroll
            for (int ntg = 0; ntg < 4; ntg += 2) {
                uint32_t vH0[4], vH1[4];
                uint32_t a0 = vbase + ntg * 4352 + kc * 32;
                ldsm4(vH0, a0);
                ldsm4(vH1, a0 + 4352);
                mma_f16(O[2*ntg],   aP, vH0 + 0);
                mma_f16(O[2*ntg+1], aP, vH0 + 2);
                mma_f16(O[2*ntg+2], aP, vH1 + 0);
                mma_f16(O[2*ntg+3], aP, vH1 + 2);
            }
        }
    }

    // ---- merge split-K halves (scratch in dead KV buffer 0) ----
    __syncthreads();
    float* sml = (float*)(sm + FKV);            // [16 warps][16 rows][2] = 2 KB
    float* Osm = (float*)(sm + FKV + 2048);     // [8 pairs][16 rows][64] fp32 = 32 KB

    if ((lane & 3) == 0) {
        sml[(wid * 16 + rl) * 2 + 0]     = m_prev0;
        sml[(wid * 16 + rl) * 2 + 1]     = l0;
        sml[(wid * 16 + rl + 8) * 2 + 0] = m_prev1;
        sml[(wid * 16 + rl + 8) * 2 + 1] = l1;
    }
    __syncthreads();

    const int pwid = wid ^ 8;
    float pm0 = sml[(pwid * 16 + rl) * 2 + 0],     pl0 = sml[(pwid * 16 + rl) * 2 + 1];
    float pm1 = sml[(pwid * 16 + rl + 8) * 2 + 0], pl1 = sml[(pwid * 16 + rl + 8) * 2 + 1];
    float M0 = fmaxf(m_prev0, pm0), M1 = fmaxf(m_prev1, pm1);
    float e0 = exp2f(m_prev0 - M0), e1 = exp2f(m_prev1 - M1);
    float pe0 = exp2f(pm0 - M0),    pe1 = exp2f(pm1 - M1);
    float L0 = l0 * e0 + pl0 * pe0;
    float L1 = l1 * e1 + pl1 * pe1;

    float* Opair = Osm + pw * 1024;
    if (khalf == 1) {
        #pragma unroll
        for (int nt = 0; nt < 8; nt++) {
            int d = nt * 8 + (lane & 3) * 2;
            float2 v0; v0.x = O[nt][0] * e0; v0.y = O[nt][1] * e0;
            float2 v1; v1.x = O[nt][2] * e1; v1.y = O[nt][3] * e1;
            *(float2*)(Opair + rl * 64 + d)       = v0;
            *(float2*)(Opair + (rl + 8) * 64 + d) = v1;
        }
    }
    __syncthreads();

    if (khalf == 0) {
        const float iL0 = 1.f / L0, iL1 = 1.f / L1;
        const int t0 = m0 + row_q;
        #pragma unroll
        for (int nt = 0; nt < 8; nt++) {
            int d = nt * 8 + (lane & 3) * 2;
            float2 ob0 = *(float2*)(Opair + rl * 64 + d);
            float2 ob1 = *(float2*)(Opair + (rl + 8) * 64 + d);
            float v0 = (O[nt][0] * e0 + ob0.x) * iL0;
            float v1 = (O[nt][1] * e0 + ob0.y) * iL0;
            float v2 = (O[nt][2] * e1 + ob1.x) * iL1;
            float v3 = (O[nt][3] * e1 + ob1.y) * iL1;

            __half h0 = __float2half_rn(v0), h1 = __float2half_rn(v1);
            size_t idx = ((size_t)bb * 1024 + t0) * 1024 + hh * 64 + d;
            *(uint32_t*)&g_c0[idx] = pack_h2(v0, v1);
            *(uint32_t*)&g_c1[idx] = pack_h2(v0 - __half2float(h0), v1 - __half2float(h1));

            __half h2 = __float2half_rn(v2), h3 = __float2half_rn(v3);
            size_t idx2 = ((size_t)bb * 1024 + t0 + 8) * 1024 + hh * 64 + d;
            *(uint32_t*)&g_c0[idx2] = pack_h2(v2, v3);
            *(uint32_t*)&g_c1[idx2] = pack_h2(v2 - __half2float(h2), v3 - __half2float(h3));
        }
    }
}

// ---------------------------------------------------------------------------
// Output projection: 128x128 tile, 512 threads, fp16 2-pass
// (ctx 2-plane, Wo single). grid (32, 8).
// ---------------------------------------------------------------------------
#define OP_SMEM (2*55296)

__global__ __launch_bounds__(512) void outproj_mma_kernel(
    const float* __restrict__ bo, float* __restrict__ out)
{
    extern __shared__ char smem[];
    const int tid = threadIdx.x;
    const int lane = tid & 31;
    const int wid = tid >> 5;
    const int wr = wid >> 2;
    const int wc = wid & 3;
    const int m0 = blockIdx.x * 128;
    const int n0 = blockIdx.y * 128;
    uint32_t sb = smem_u32(smem);

    float acc[2][4][4];
    #pragma unroll
    for (int mt = 0; mt < 2; mt++)
        #pragma unroll
        for (int nt = 0; nt < 4; nt++)
            #pragma unroll
            for (int j = 0; j < 4; j++) acc[mt][nt][j] = 0.f;

    const char* planes[3] = {
        (const char*)(g_c0 + (size_t)m0 * 1024), (const char*)(g_c1 + (size_t)m0 * 1024),
        (const char*)(g_wo0 + (size_t)n0 * 1024) };

    auto issue = [&](int ks) {
        uint32_t base = sb + (uint32_t)(ks & 1) * 55296;
        #pragma unroll
        for (int j = 0; j < 6; j++) {
            int id = j * 512 + tid;
            int plane = id >> 10;
            int wp = id & 1023;
            int row = wp >> 3, c = wp & 7;
            CP16(base + plane * 18432 + row * 144 + c * 16,
                 planes[plane] + (size_t)row * 2048 + (size_t)ks * 128 + c * 16);
        }
    };

    uint32_t aaddr[2];
    #pragma unroll
    for (int mt = 0; mt < 2; mt++)
        aaddr[mt] = sb + (uint32_t)((wr * 32 + mt * 16 + (lane & 15)) * 144 + (lane >> 4) * 16);

    const uint32_t bgrp = sb + 36864
        + (uint32_t)((wc * 32 + ((lane >> 4) << 3) + (lane & 7)) * 144)
        + ((lane & 8) ? 16u : 0u);

    issue(0); CP_COMMIT();

    for (int ks = 0; ks < 16; ks++) {
        CP_WAIT(0);
        __syncthreads();
        if (ks + 1 < 16) { issue(ks + 1); CP_COMMIT(); }

        const uint32_t soff = (uint32_t)(ks & 1) * 55296;
        #pragma unroll
        for (int kc = 0; kc < 4; kc++) {
            const uint32_t ko = soff + kc * 32;
            uint32_t aH[2][4], aL[2][4];
            #pragma unroll
            for (int mt = 0; mt < 2; mt++) {
                ldsm4(aH[mt], aaddr[mt] + ko);
                ldsm4(aL[mt], aaddr[mt] + ko + 18432);
            }
            uint32_t bH01[4], bH23[4];
            ldsm4(bH01, bgrp + ko);
            ldsm4(bH23, bgrp + ko + 2304);

            #pragma unroll
            for (int mt = 0; mt < 2; mt++) {
                mma_f16(acc[mt][0], aH[mt], bH01 + 0);
                mma_f16(acc[mt][1], aH[mt], bH01 + 2);
                mma_f16(acc[mt][2], aH[mt], bH23 + 0);
                mma_f16(acc[mt][3], aH[mt], bH23 + 2);
            }
            #pragma unroll
            for (int mt = 0; mt < 2; mt++) {
                mma_f16(acc[mt][0], aL[mt], bH01 + 0);
                mma_f16(acc[mt][1], aL[mt], bH01 + 2);
                mma_f16(acc[mt][2], aL[mt], bH23 + 0);
                mma_f16(acc[mt][3], aL[mt], bH23 + 2);
            }
        }
    }

    #pragma unroll
    for (int mt = 0; mt < 2; mt++)
        #pragma unroll
        for (int nt = 0; nt < 4; nt++) {
            int f = n0 + wc * 32 + nt * 8 + (lane & 3) * 2;
            float bz0 = bo[f], bz1 = bo[f + 1];
            #pragma unroll
            for (int half = 0; half < 2; half++) {
                int m = m0 + wr * 32 + mt * 16 + (lane >> 2) + half * 8;
                float2 v;
                v.x = acc[mt][nt][half * 2 + 0] + bz0;
                v.y = acc[mt][nt][half * 2 + 1] + bz1;
                *(float2*)&out[(size_t)m * 1024 + f] = v;
            }
        }
}

// ---------------------------------------------------------------------------
extern "C" void kernel_launch(void* const* d_in, const int* in_sizes, int n_in,
                              void* d_out, int out_size)
{
    (void)in_sizes; (void)n_in; (void)out_size;
    const float* x     = (const float*)d_in[0];
    const float* noise = (const float*)d_in[1];
    const float* Wq    = (const float*)d_in[2];
    const float* bq    = (const float*)d_in[3];
    const float* Wk    = (const float*)d_in[4];
    const float* bk    = (const float*)d_in[5];
    const float* Wv    = (const float*)d_in[6];
    const float* bv    = (const float*)d_in[7];
    const float* Wo    = (const float*)d_in[8];
    const float* bo    = (const float*)d_in[9];
    const float* theta = (const float*)d_in[10];
    // d_in[11] = corr_w: unused (per-head bias cancels in softmax)
    float* out = (float*)d_out;

    cudaFuncSetAttribute(flash_kernel,
        cudaFuncAttributeMaxDynamicSharedMemorySize, FL_SMEM);
    cudaFuncSetAttribute(qkv_mma_kernel,
        cudaFuncAttributeMaxDynamicSharedMemorySize, GP_SMEM);
    cudaFuncSetAttribute(outproj_mma_kernel,
        cudaFuncAttributeMaxDynamicSharedMemorySize, OP_SMEM);

    split_all_kernel<<<4096, 256>>>(x, Wq, Wk, Wv, Wo);
    qkv_mma_kernel<<<dim3(32, 24), 512, GP_SMEM>>>(bq, bk, bv);
    flash_kernel<<<dim3(8, 64), 512, FL_SMEM>>>(noise, theta);
    outproj_mma_kernel<<<dim3(32, 8), 512, OP_SMEM>>>(bo, out);
}

// round 17
// speedup vs baseline: 1.7441x; 1.0826x over previous
#include <cuda_runtime.h>
#include <cuda_fp16.h>
#include <cstdint>
#include <math.h>

// Problem: B=4, H=16, T=1024, D=64, E=1024, M=B*T=4096, BH=64
// fp16 split GEMMs. qkv: 2-pass for q/k, 1-pass for v. scores: 2-pass
// (q 2-plane, k single). P@V: 1-pass. outproj: 1-pass (ctx single, Wo single).

// ---------------------------------------------------------------------------
// Device-global scratch (fp16)
// ---------------------------------------------------------------------------
__device__ __half g_xs0[4194304], g_xs1[4194304];   // x split   [4096][1024]
__device__ __half g_wb0[3145728];                   // Wq|Wk|Wv single plane
__device__ __half g_wo0[1048576];                   // Wo single plane
__device__ __half g_q0[4194304],  g_q1[4194304];    // q (scaled 0.125*log2e) 2-plane
__device__ __half g_k0[4194304];                    // k single plane [bh][s][d]
__device__ __half g_vt0[4194304];                   // vT single plane [bh][d][s]
__device__ __half g_c0[4194304];                    // ctx single plane [m][e]

// ---------------------------------------------------------------------------
// PTX helpers
// ---------------------------------------------------------------------------
__device__ __forceinline__ uint32_t smem_u32(const void* p) {
    uint32_t a;
    asm("{ .reg .u64 t; cvta.to.shared.u64 t, %1; cvt.u32.u64 %0, t; }" : "=r"(a) : "l"(p));
    return a;
}

__device__ __forceinline__ void ldsm4(uint32_t r[4], uint32_t addr) {
    asm volatile("ldmatrix.sync.aligned.m8n8.x4.shared.b16 {%0,%1,%2,%3}, [%4];"
        : "=r"(r[0]), "=r"(r[1]), "=r"(r[2]), "=r"(r[3]) : "r"(addr));
}

__device__ __forceinline__ void mma_f16(float* c, const uint32_t* a, const uint32_t* b) {
    asm volatile(
        "mma.sync.aligned.m16n8k16.row.col.f32.f16.f16.f32 "
        "{%0,%1,%2,%3}, {%4,%5,%6,%7}, {%8,%9}, {%0,%1,%2,%3};\n"
        : "+f"(c[0]), "+f"(c[1]), "+f"(c[2]), "+f"(c[3])
        : "r"(a[0]), "r"(a[1]), "r"(a[2]), "r"(a[3]), "r"(b[0]), "r"(b[1]));
}

#define CP16(dst, src) \
    asm volatile("cp.async.cg.shared.global [%0], [%1], 16;" :: "r"(dst), "l"(src))
#define CP_COMMIT() asm volatile("cp.async.commit_group;")
#define CP_WAIT(N)  asm volatile("cp.async.wait_group %0;" :: "n"(N))

__device__ __forceinline__ uint32_t pack_h2(float x, float y) {
    __half2 h = __floats2half2_rn(x, y);
    return *(uint32_t*)&h;
}

// ---------------------------------------------------------------------------
// Merged split kernel: x -> 2 fp16 planes; Wq/Wk/Wv/Wo -> 1 plane each.
// ---------------------------------------------------------------------------
__global__ __launch_bounds__(256) void split_all_kernel(
    const float* __restrict__ x,  const float* __restrict__ Wq,
    const float* __restrict__ Wk, const float* __restrict__ Wv,
    const float* __restrict__ Wo)
{
    const int NX = 1048576;
    const int NW = 262144;
    const int NT = NX + 4 * NW;
    for (int i4 = blockIdx.x * 256 + threadIdx.x; i4 < NT; i4 += gridDim.x * 256) {
        const float* src; __half *d0; int idx; bool lo = false;
        if (i4 < NX) { src = x; d0 = g_xs0; idx = i4; lo = true; }
        else {
            int r = i4 - NX; int w = r / NW; idx = r - w * NW;
            if (w == 0)      { src = Wq; d0 = g_wb0; }
            else if (w == 1) { src = Wk; d0 = g_wb0 + 1048576; }
            else if (w == 2) { src = Wv; d0 = g_wb0 + 2097152; }
            else             { src = Wo; d0 = g_wo0; }
        }
        float4 a = ((const float4*)src)[idx];
        __half h0 = __float2half_rn(a.x), h1 = __float2half_rn(a.y);
        __half h2 = __float2half_rn(a.z), h3 = __float2half_rn(a.w);
        uint2 vh;
        { __half2 p01; p01.x = h0; p01.y = h1;
          __half2 p23; p23.x = h2; p23.y = h3;
          vh.x = *(uint32_t*)&p01; vh.y = *(uint32_t*)&p23; }
        *(uint2*)(d0 + 4 * (size_t)idx) = vh;
        if (lo) {
            uint2 vl;
            vl.x = pack_h2(a.x - __half2float(h0), a.y - __half2float(h1));
            vl.y = pack_h2(a.z - __half2float(h2), a.w - __half2float(h3));
            *(uint2*)(g_xs1 + 4 * (size_t)idx) = vl;
        }
    }
}

// ---------------------------------------------------------------------------
// QKV projection: 128x128 tile, 512 threads. fp16 2-pass for q/k blocks,
// 1-pass for v blocks (which==2 skips the x-residual pass).
// grid (32, 24). Smem/stage 55296: A0@0 A1@18432 B@36864.
// ---------------------------------------------------------------------------
#define GP_SMEM (2*55296)

__global__ __launch_bounds__(512) void qkv_mma_kernel(
    const float* __restrict__ bq, const float* __restrict__ bk,
    const float* __restrict__ bv)
{
    extern __shared__ char smem[];
    const int tid = threadIdx.x;
    const int lane = tid & 31;
    const int wid = tid >> 5;
    const int wr = wid >> 2;
    const int wc = wid & 3;
    const int m0 = blockIdx.x * 128;
    const int n0 = blockIdx.y * 128;
    const int which = n0 >> 10;
    const bool do_lo = (which != 2);
    uint32_t sb = smem_u32(smem);

    float acc[2][4][4];
    #pragma unroll
    for (int mt = 0; mt < 2; mt++)
        #pragma unroll
        for (int nt = 0; nt < 4; nt++)
            #pragma unroll
            for (int j = 0; j < 4; j++) acc[mt][nt][j] = 0.f;

    const char* planes[3] = {
        (const char*)(g_xs0 + (size_t)m0 * 1024), (const char*)(g_xs1 + (size_t)m0 * 1024),
        (const char*)(g_wb0 + (size_t)n0 * 1024) };

    auto issue = [&](int ks) {
        uint32_t base = sb + (uint32_t)(ks & 1) * 55296;
        #pragma unroll
        for (int j = 0; j < 6; j++) {
            int id = j * 512 + tid;
            int plane = id >> 10;
            int wp = id & 1023;
            int row = wp >> 3, c = wp & 7;
            CP16(base + plane * 18432 + row * 144 + c * 16,
                 planes[plane] + (size_t)row * 2048 + (size_t)ks * 128 + c * 16);
        }
    };

    uint32_t aaddr[2];
    #pragma unroll
    for (int mt = 0; mt < 2; mt++)
        aaddr[mt] = sb + (uint32_t)((wr * 32 + mt * 16 + (lane & 15)) * 144 + (lane >> 4) * 16);

    const uint32_t bgrp = sb + 36864
        + (uint32_t)((wc * 32 + ((lane >> 4) << 3) + (lane & 7)) * 144)
        + ((lane & 8) ? 16u : 0u);

    issue(0); CP_COMMIT();

    for (int ks = 0; ks < 16; ks++) {
        CP_WAIT(0);
        __syncthreads();
        if (ks + 1 < 16) { issue(ks + 1); CP_COMMIT(); }

        const uint32_t soff = (uint32_t)(ks & 1) * 55296;
        #pragma unroll
        for (int kc = 0; kc < 4; kc++) {
            const uint32_t ko = soff + kc * 32;
            uint32_t aH[2][4];
            #pragma unroll
            for (int mt = 0; mt < 2; mt++)
                ldsm4(aH[mt], aaddr[mt] + ko);
            uint32_t bH01[4], bH23[4];
            ldsm4(bH01, bgrp + ko);
            ldsm4(bH23, bgrp + ko + 2304);

            #pragma unroll
            for (int mt = 0; mt < 2; mt++) {
                mma_f16(acc[mt][0], aH[mt], bH01 + 0);
                mma_f16(acc[mt][1], aH[mt], bH01 + 2);
                mma_f16(acc[mt][2], aH[mt], bH23 + 0);
                mma_f16(acc[mt][3], aH[mt], bH23 + 2);
            }
            if (do_lo) {
                uint32_t aL[2][4];
                #pragma unroll
                for (int mt = 0; mt < 2; mt++)
                    ldsm4(aL[mt], aaddr[mt] + ko + 18432);
                #pragma unroll
                for (int mt = 0; mt < 2; mt++) {
                    mma_f16(acc[mt][0], aL[mt], bH01 + 0);
                    mma_f16(acc[mt][1], aL[mt], bH01 + 2);
                    mma_f16(acc[mt][2], aL[mt], bH23 + 0);
                    mma_f16(acc[mt][3], aL[mt], bH23 + 2);
                }
            }
        }
    }

    const int fbase = n0 & 1023;
    const float* bias = (which == 0) ? bq : (which == 1) ? bk : bv;
    const float psc = (which == 0) ? 0.125f * 1.44269504088896340736f : 1.0f;

    #pragma unroll
    for (int mt = 0; mt < 2; mt++) {
        #pragma unroll
        for (int nt = 0; nt < 4; nt++) {
            int f = fbase + wc * 32 + nt * 8 + (lane & 3) * 2;
            int h = f >> 6, d = f & 63;
            float bz0 = bias[f], bz1 = bias[f + 1];
            #pragma unroll
            for (int half = 0; half < 2; half++) {
                int m = m0 + wr * 32 + mt * 16 + (lane >> 2) + half * 8;
                int b = m >> 10, t = m & 1023;
                float v0 = (acc[mt][nt][half * 2 + 0] + bz0) * psc;
                float v1 = (acc[mt][nt][half * 2 + 1] + bz1) * psc;
                __half h0 = __float2half_rn(v0);
                __half h1 = __float2half_rn(v1);
                uint32_t ph = pack_h2(v0, v1);
                if (which == 0) {
                    uint32_t pl = pack_h2(v0 - __half2float(h0), v1 - __half2float(h1));
                    size_t idx = (((size_t)(b * 16 + h)) * 1024 + t) * 64 + d;
                    *(uint32_t*)&g_q0[idx] = ph;
                    *(uint32_t*)&g_q1[idx] = pl;
                } else if (which == 1) {
                    size_t idx = (((size_t)(b * 16 + h)) * 1024 + t) * 64 + d;
                    *(uint32_t*)&g_k0[idx] = ph;
                } else {
                    size_t base = ((size_t)(b * 16 + h) * 64 + d) * 1024 + t;
                    g_vt0[base] = h0;
                    g_vt0[base + 1024] = h1;
                }
            }
        }
    }
}

// ---------------------------------------------------------------------------
// Flash attention: 128-row Q tiles, split-K warp pairs, grid (8, 64),
// 512 threads. Scores 2-pass (qH/qL vs kH); P@V 1-pass. Base-2 softmax.
// ctx written single-plane.
// ---------------------------------------------------------------------------
#define FQ0 0
#define FQ1 18432
#define FKV 36864
#define FKV_STRIDE 35840
#define FV0_OFF 18432
#define FL_SMEM (36864 + 2*35840)

__global__ __launch_bounds__(512, 1) void flash_kernel(
    const float* __restrict__ noise, const float* __restrict__ theta)
{
    extern __shared__ char sm[];
    __half* q0s = (__half*)(sm + FQ0);
    __half* q1s = (__half*)(sm + FQ1);
    uint32_t sb = smem_u32(sm);

    const int tid = threadIdx.x;
    const int lane = tid & 31;
    const int wid = tid >> 5;
    const int pw = wid & 7;
    const int khalf = wid >> 3;
    const int m0 = blockIdx.x * 128;
    const int bh = blockIdx.y;
    const int bb = bh >> 4, hh = bh & 15;

    const char* gk0 = (const char*)(g_k0 + (size_t)bh * 65536);
    const char* gv0 = (const char*)(g_vt0 + (size_t)bh * 65536);

    auto issue = [&](int s0, int b) {
        uint32_t base = sb + FKV + (uint32_t)b * FKV_STRIDE;
        #pragma unroll
        for (int j = 0; j < 2; j++) {
            int idx = j * 512 + tid;       // 0..1023
            int row = idx >> 3, c = idx & 7;
            CP16(base + row * 144 + c * 16,
                 gk0 + (size_t)(s0 + row) * 128 + c * 16);
            int vrow = idx >> 4, vc = idx & 15;
            CP16(base + FV0_OFF + vrow * 272 + vc * 16,
                 gv0 + (size_t)vrow * 2048 + (size_t)s0 * 2 + vc * 16);
        }
    };

    issue(0, 0); CP_COMMIT();

    float Tm = 0.f;
    #pragma unroll
    for (int h = 0; h < 16; h++) {
        float sg = 1.f / (1.f + expf(-theta[h]));
        Tm += fabsf(sinf(2.f * sg * 1.57079632679489662f));
    }
    Tm *= (1.f / 16.f);
    const float inv_keep = 1.f / (1.f - Tm + 1e-8f);

    // Q tile (128 rows x 64 d, 2 planes)
    {
        const __half* gq0 = g_q0 + (size_t)bh * 65536 + (size_t)m0 * 64;
        const __half* gq1 = g_q1 + (size_t)bh * 65536 + (size_t)m0 * 64;
        #pragma unroll
        for (int i = 0; i < 2; i++) {
            int idx = i * 512 + tid;
            int row = idx >> 3, c = idx & 7;
            *(float4*)(q0s + row * 72 + c * 8) = *(const float4*)(gq0 + row * 64 + c * 8);
            *(float4*)(q1s + row * 72 + c * 8) = *(const float4*)(gq1 + row * 64 + c * 8);
        }
    }
    __syncthreads();

    uint32_t qH[4][4], qL[4][4];
    {
        uint32_t qa0 = smem_u32(q0s + (pw * 16 + (lane & 15)) * 72 + (lane >> 4) * 8);
        uint32_t qa1 = smem_u32(q1s + (pw * 16 + (lane & 15)) * 72 + (lane >> 4) * 8);
        #pragma unroll
        for (int kc = 0; kc < 4; kc++) {
            ldsm4(qH[kc], qa0 + kc * 32);
            ldsm4(qL[kc], qa1 + kc * 32);
        }
    }

    const uint32_t lrow8 = ((lane >> 4) << 3) + (lane & 7);
    const uint32_t khoff = (lane & 8) ? 16u : 0u;
    const uint32_t kgrp = lrow8 * 144 + khoff + (uint32_t)khalf * 9216;
    const uint32_t vgrp = lrow8 * 272 + khoff + (uint32_t)khalf * 128;

    const int rl = lane >> 2;
    const int row_q = pw * 16 + rl;
    const float* nz_base = noise + (size_t)bh * 1048576
                         + (size_t)(m0 + row_q) * 1024 + khalf * 64 + (lane & 3) * 2;

    float m_prev0 = -1e30f, m_prev1 = -1e30f;
    float l0 = 0.f, l1 = 0.f;
    float O[8][4];
    #pragma unroll
    for (int nt = 0; nt < 8; nt++)
        #pragma unroll
        for (int j = 0; j < 4; j++) O[nt][j] = 0.f;

    for (int it = 0; it < 8; it++) {
        const int s0 = it * 128;
        const int buf = it & 1;
        CP_WAIT(0);
        __syncthreads();
        if (it + 1 < 8) issue(s0 + 128, buf ^ 1);
        CP_COMMIT();

        const uint32_t kbase = sb + FKV + (uint32_t)buf * FKV_STRIDE + kgrp;
        const uint32_t vbase = sb + FKV + (uint32_t)buf * FKV_STRIDE + FV0_OFF + vgrp;

        // ---- scores (16 x 64): 2-pass qH/qL vs kH ----
        float Sa[8][4];
        #pragma unroll
        for (int nt = 0; nt < 8; nt++)
            #pragma unroll
            for (int j = 0; j < 4; j++) Sa[nt][j] = 0.f;

        #pragma unroll
        for (int kc = 0; kc < 4; kc++) {
            #pragma unroll
            for (int ntg = 0; ntg < 4; ntg += 2) {
                uint32_t tH0[4], tH1[4];
                uint32_t a0 = kbase + ntg * 2304 + kc * 32;
                ldsm4(tH0, a0);
                ldsm4(tH1, a0 + 2304);
                mma_f16(Sa[2*ntg],   qH[kc], tH0 + 0);
                mma_f16(Sa[2*ntg+1], qH[kc], tH0 + 2);
                mma_f16(Sa[2*ntg+2], qH[kc], tH1 + 0);
                mma_f16(Sa[2*ntg+3], qH[kc], tH1 + 2);
                mma_f16(Sa[2*ntg],   qL[kc], tH0 + 0);
                mma_f16(Sa[2*ntg+1], qL[kc], tH0 + 2);
                mma_f16(Sa[2*ntg+2], qL[kc], tH1 + 0);
                mma_f16(Sa[2*ntg+3], qL[kc], tH1 + 2);
            }
        }

        // ---- per-warp online softmax (base-2) ----
        float mt0 = -1e30f, mt1 = -1e30f;
        #pragma unroll
        for (int nt = 0; nt < 8; nt++) {
            mt0 = fmaxf(mt0, fmaxf(Sa[nt][0], Sa[nt][1]));
            mt1 = fmaxf(mt1, fmaxf(Sa[nt][2], Sa[nt][3]));
        }
        mt0 = fmaxf(mt0, __shfl_xor_sync(0xffffffffu, mt0, 1));
        mt0 = fmaxf(mt0, __shfl_xor_sync(0xffffffffu, mt0, 2));
        mt1 = fmaxf(mt1, __shfl_xor_sync(0xffffffffu, mt1, 1));
        mt1 = fmaxf(mt1, __shfl_xor_sync(0xffffffffu, mt1, 2));

        float mn0 = fmaxf(m_prev0, mt0), mn1 = fmaxf(m_prev1, mt1);
        float f0 = exp2f(m_prev0 - mn0), f1 = exp2f(m_prev1 - mn1);
        m_prev0 = mn0; m_prev1 = mn1;
        l0 *= f0; l1 *= f1;
        #pragma unroll
        for (int nt = 0; nt < 8; nt++) {
            O[nt][0] *= f0; O[nt][1] *= f0;
            O[nt][2] *= f1; O[nt][3] *= f1;
        }

        float rs0 = 0.f, rs1 = 0.f;
        #pragma unroll
        for (int nt = 0; nt < 8; nt++) {
            Sa[nt][0] = exp2f(Sa[nt][0] - mn0);
            Sa[nt][1] = exp2f(Sa[nt][1] - mn0);
            Sa[nt][2] = exp2f(Sa[nt][2] - mn1);
            Sa[nt][3] = exp2f(Sa[nt][3] - mn1);
            rs0 += Sa[nt][0] + Sa[nt][1];
            rs1 += Sa[nt][2] + Sa[nt][3];
        }
        rs0 += __shfl_xor_sync(0xffffffffu, rs0, 1);
        rs0 += __shfl_xor_sync(0xffffffffu, rs0, 2);
        rs1 += __shfl_xor_sync(0xffffffffu, rs1, 1);
        rs1 += __shfl_xor_sync(0xffffffffu, rs1, 2);
        l0 += rs0; l1 += rs1;

        // ---- dropout ----
        const float* nz0 = nz_base + s0;
        #pragma unroll
        for (int nt = 0; nt < 8; nt++) {
            float2 a = *(const float2*)(nz0 + nt * 8);
            float2 b = *(const float2*)(nz0 + 8192 + nt * 8);
            Sa[nt][0] *= (a.x > Tm) ? inv_keep : 0.f;
            Sa[nt][1] *= (a.y > Tm) ? inv_keep : 0.f;
            Sa[nt][2] *= (b.x > Tm) ? inv_keep : 0.f;
            Sa[nt][3] *= (b.y > Tm) ? inv_keep : 0.f;
        }

        // ---- P @ V: 1-pass ----
        #pragma unroll
        for (int kc = 0; kc < 4; kc++) {
            uint32_t aP[4];
            aP[0] = pack_h2(Sa[2*kc][0],   Sa[2*kc][1]);
            aP[1] = pack_h2(Sa[2*kc][2],   Sa[2*kc][3]);
            aP[2] = pack_h2(Sa[2*kc+1][0], Sa[2*kc+1][1]);
            aP[3] = pack_h2(Sa[2*kc+1][2], Sa[2*kc+1][3]);
            #pragma unroll
            for (int ntg = 0; ntg < 4; ntg += 2) {
                uint32_t vH0[4], vH1[4];
                uint32_t a0 = vbase + ntg * 4352 + kc * 32;
                ldsm4(vH0, a0);
                ldsm4(vH1, a0 + 4352);
                mma_f16(O[2*ntg],   aP, vH0 + 0);
                mma_f16(O[2*ntg+1], aP, vH0 + 2);
                mma_f16(O[2*ntg+2], aP, vH1 + 0);
                mma_f16(O[2*ntg+3], aP, vH1 + 2);
            }
        }
    }

    // ---- merge split-K halves (scratch in dead KV buffer 0) ----
    __syncthreads();
    float* sml = (float*)(sm + FKV);            // [16 warps][16 rows][2] = 2 KB
    float* Osm = (float*)(sm + FKV + 2048);     // [8 pairs][16 rows][64] fp32 = 32 KB

    if ((lane & 3) == 0) {
        sml[(wid * 16 + rl) * 2 + 0]     = m_prev0;
        sml[(wid * 16 + rl) * 2 + 1]     = l0;
        sml[(wid * 16 + rl + 8) * 2 + 0] = m_prev1;
        sml[(wid * 16 + rl + 8) * 2 + 1] = l1;
    }
    __syncthreads();

    const int pwid = wid ^ 8;
    float pm0 = sml[(pwid * 16 + rl) * 2 + 0],     pl0 = sml[(pwid * 16 + rl) * 2 + 1];
    float pm1 = sml[(pwid * 16 + rl + 8) * 2 + 0], pl1 = sml[(pwid * 16 + rl + 8) * 2 + 1];
    float M0 = fmaxf(m_prev0, pm0), M1 = fmaxf(m_prev1, pm1);
    float e0 = exp2f(m_prev0 - M0), e1 = exp2f(m_prev1 - M1);
    float pe0 = exp2f(pm0 - M0),    pe1 = exp2f(pm1 - M1);
    float L0 = l0 * e0 + pl0 * pe0;
    float L1 = l1 * e1 + pl1 * pe1;

    float* Opair = Osm + pw * 1024;
    if (khalf == 1) {
        #pragma unroll
        for (int nt = 0; nt < 8; nt++) {
            int d = nt * 8 + (lane & 3) * 2;
            float2 v0; v0.x = O[nt][0] * e0; v0.y = O[nt][1] * e0;
            float2 v1; v1.x = O[nt][2] * e1; v1.y = O[nt][3] * e1;
            *(float2*)(Opair + rl * 64 + d)       = v0;
            *(float2*)(Opair + (rl + 8) * 64 + d) = v1;
        }
    }
    __syncthreads();

    if (khalf == 0) {
        const float iL0 = 1.f / L0, iL1 = 1.f / L1;
        const int t0 = m0 + row_q;
        #pragma unroll
        for (int nt = 0; nt < 8; nt++) {
            int d = nt * 8 + (lane & 3) * 2;
            float2 ob0 = *(float2*)(Opair + rl * 64 + d);
            float2 ob1 = *(float2*)(Opair + (rl + 8) * 64 + d);
            float v0 = (O[nt][0] * e0 + ob0.x) * iL0;
            float v1 = (O[nt][1] * e0 + ob0.y) * iL0;
            float v2 = (O[nt][2] * e1 + ob1.x) * iL1;
            float v3 = (O[nt][3] * e1 + ob1.y) * iL1;

            size_t idx = ((size_t)bb * 1024 + t0) * 1024 + hh * 64 + d;
            *(uint32_t*)&g_c0[idx] = pack_h2(v0, v1);
            size_t idx2 = ((size_t)bb * 1024 + t0 + 8) * 1024 + hh * 64 + d;
            *(uint32_t*)&g_c0[idx2] = pack_h2(v2, v3);
        }
    }
}

// ---------------------------------------------------------------------------
// Output projection: 128x128 tile, 512 threads, fp16 1-pass
// (ctx single, Wo single). grid (32, 8). Smem/stage 36864: A@0 B@18432.
// ---------------------------------------------------------------------------
#define OP_SMEM (2*36864)

__global__ __launch_bounds__(512) void outproj_mma_kernel(
    const float* __restrict__ bo, float* __restrict__ out)
{
    extern __shared__ char smem[];
    const int tid = threadIdx.x;
    const int lane = tid & 31;
    const int wid = tid >> 5;
    const int wr = wid >> 2;
    const int wc = wid & 3;
    const int m0 = blockIdx.x * 128;
    const int n0 = blockIdx.y * 128;
    uint32_t sb = smem_u32(smem);

    float acc[2][4][4];
    #pragma unroll
    for (int mt = 0; mt < 2; mt++)
        #pragma unroll
        for (int nt = 0; nt < 4; nt++)
            #pragma unroll
            for (int j = 0; j < 4; j++) acc[mt][nt][j] = 0.f;

    const char* planes[2] = {
        (const char*)(g_c0 + (size_t)m0 * 1024),
        (const char*)(g_wo0 + (size_t)n0 * 1024) };

    // 2 planes x 128 rows x 8 chunks = 2048 chunks, 4 per thread
    auto issue = [&](int ks) {
        uint32_t base = sb + (uint32_t)(ks & 1) * 36864;
        #pragma unroll
        for (int j = 0; j < 4; j++) {
            int id = j * 512 + tid;
            int plane = id >> 10;
            int wp = id & 1023;
            int row = wp >> 3, c = wp & 7;
            CP16(base + plane * 18432 + row * 144 + c * 16,
                 planes[plane] + (size_t)row * 2048 + (size_t)ks * 128 + c * 16);
        }
    };

    uint32_t aaddr[2];
    #pragma unroll
    for (int mt = 0; mt < 2; mt++)
        aaddr[mt] = sb + (uint32_t)((wr * 32 + mt * 16 + (lane & 15)) * 144 + (lane >> 4) * 16);

    const uint32_t bgrp = sb + 18432
        + (uint32_t)((wc * 32 + ((lane >> 4) << 3) + (lane & 7)) * 144)
        + ((lane & 8) ? 16u : 0u);

    issue(0); CP_COMMIT();

    for (int ks = 0; ks < 16; ks++) {
        CP_WAIT(0);
        __syncthreads();
        if (ks + 1 < 16) { issue(ks + 1); CP_COMMIT(); }

        const uint32_t soff = (uint32_t)(ks & 1) * 36864;
        #pragma unroll
        for (int kc = 0; kc < 4; kc++) {
            const uint32_t ko = soff + kc * 32;
            uint32_t aH[2][4];
            #pragma unroll
            for (int mt = 0; mt < 2; mt++)
                ldsm4(aH[mt], aaddr[mt] + ko);
            uint32_t bH01[4], bH23[4];
            ldsm4(bH01, bgrp + ko);
            ldsm4(bH23, bgrp + ko + 2304);

            #pragma unroll
            for (int mt = 0; mt < 2; mt++) {
                mma_f16(acc[mt][0], aH[mt], bH01 + 0);
                mma_f16(acc[mt][1], aH[mt], bH01 + 2);
                mma_f16(acc[mt][2], aH[mt], bH23 + 0);
                mma_f16(acc[mt][3], aH[mt], bH23 + 2);
            }
        }
    }

    #pragma unroll
    for (int mt = 0; mt < 2; mt++)
        #pragma unroll
        for (int nt = 0; nt < 4; nt++) {
            int f = n0 + wc * 32 + nt * 8 + (lane & 3) * 2;
            float bz0 = bo[f], bz1 = bo[f + 1];
            #pragma unroll
            for (int half = 0; half < 2; half++) {
                int m = m0 + wr * 32 + mt * 16 + (lane >> 2) + half * 8;
                float2 v;
                v.x = acc[mt][nt][half * 2 + 0] + bz0;
                v.y = acc[mt][nt][half * 2 + 1] + bz1;
                *(float2*)&out[(size_t)m * 1024 + f] = v;
            }
        }
}

// ---------------------------------------------------------------------------
extern "C" void kernel_launch(void* const* d_in, const int* in_sizes, int n_in,
                              void* d_out, int out_size)
{
    (void)in_sizes; (void)n_in; (void)out_size;
    const float* x     = (const float*)d_in[0];
    const float* noise = (const float*)d_in[1];
    const float* Wq    = (const float*)d_in[2];
    const float* bq    = (const float*)d_in[3];
    const float* Wk    = (const float*)d_in[4];
    const float* bk    = (const float*)d_in[5];
    const float* Wv    = (const float*)d_in[6];
    const float* bv    = (const float*)d_in[7];
    const float* Wo    = (const float*)d_in[8];
    const float* bo    = (const float*)d_in[9];
    const float* theta = (const float*)d_in[10];
    // d_in[11] = corr_w: unused (per-head bias cancels in softmax)
    float* out = (float*)d_out;

    cudaFuncSetAttribute(flash_kernel,
        cudaFuncAttributeMaxDynamicSharedMemorySize, FL_SMEM);
    cudaFuncSetAttribute(qkv_mma_kernel,
        cudaFuncAttributeMaxDynamicSharedMemorySize, GP_SMEM);
    cudaFuncSetAttribute(outproj_mma_kernel,
        cudaFuncAttributeMaxDynamicSharedMemorySize, OP_SMEM);

    split_all_kernel<<<4096, 256>>>(x, Wq, Wk, Wv, Wo);
    qkv_mma_kernel<<<dim3(32, 24), 512, GP_SMEM>>>(bq, bk, bv);
    flash_kernel<<<dim3(8, 64), 512, FL_SMEM>>>(noise, theta);
    outproj_mma_kernel<<<dim3(32, 8), 512, OP_SMEM>>>(bo, out);
}